// round 14
// baseline (speedup 1.0000x reference)
#include <cuda_runtime.h>
#include <cuda_fp16.h>
#include <cstdint>

// ---------------------------------------------------------------------------
// NEZHA-style MHA, all single-fp16 HMMA, cp.async double-buffered mainloops
// (single barrier per iteration), fp16 scores; pbconv on side stream;
// fused/av/out-proj j-half pipelined. B=4, S=1024, H=12, DK=DV=64, DM=768.
// ---------------------------------------------------------------------------

#define S 1024
#define Hh 12
#define BH 48
#define NEGV (-1e12f)

// ---------------- scratch -----------------------------------------------------
__device__ float g_attn[(size_t)4 * S * 768];

__device__ __align__(16) __half g_s16[(size_t)BH * S * S];      // scores, 100 MB
__device__ __align__(16) __half g_x16[(size_t)3 * 4096 * 768];
__device__ __align__(16) __half g_wt16[(size_t)4 * 768 * 768];
__device__ __align__(16) __half g_q16[(size_t)BH * S * 64];
__device__ __align__(16) __half g_k16[(size_t)BH * S * 64];
__device__ __align__(16) __half g_vwt16[(size_t)BH * 64 * S];   // [bh][d][s]
__device__ __align__(16) __half g_A16[(size_t)BH * S * S];      // 100 MB
__device__ __align__(16) __half g_pb16[(size_t)S * S * 64];     // [j][k][d] 128MB

// ---------------- helpers -----------------------------------------------------
__device__ __forceinline__ uint32_t smem_to_u32(const void* p) {
    uint32_t a;
    asm("{ .reg .u64 t; cvta.to.shared.u64 t, %1; cvt.u32.u64 %0, t; }"
        : "=r"(a) : "l"(p));
    return a;
}
#define SWZ(o)    ((uint32_t)(o) ^ ((((uint32_t)(o)) >> 3) & 0x70))
#define SWZ256(o) ((uint32_t)(o) ^ ((((uint32_t)(o)) >> 4) & 0x70))

__device__ __forceinline__ void ldmx4(uint32_t* r, uint32_t a) {
    asm volatile("ldmatrix.sync.aligned.m8n8.x4.shared.b16 {%0,%1,%2,%3}, [%4];"
                 : "=r"(r[0]), "=r"(r[1]), "=r"(r[2]), "=r"(r[3]) : "r"(a));
}
__device__ __forceinline__ void ldmx2t(uint32_t* r, uint32_t a) {
    asm volatile("ldmatrix.sync.aligned.m8n8.x2.trans.shared.b16 {%0,%1}, [%2];"
                 : "=r"(r[0]), "=r"(r[1]) : "r"(a));
}
__device__ __forceinline__ void mmah(float* c, const uint32_t* a,
                                     const uint32_t* b) {
    asm volatile(
        "mma.sync.aligned.m16n8k16.row.col.f32.f16.f16.f32 "
        "{%0,%1,%2,%3},{%4,%5,%6,%7},{%8,%9},{%0,%1,%2,%3};"
        : "+f"(c[0]), "+f"(c[1]), "+f"(c[2]), "+f"(c[3])
        : "r"(a[0]), "r"(a[1]), "r"(a[2]), "r"(a[3]), "r"(b[0]), "r"(b[1]));
}
__device__ __forceinline__ uint32_t hpack(float a, float b) {
    __half2 t = __floats2half2_rn(a, b);
    return *(uint32_t*)&t;
}
__device__ __forceinline__ uint2 cvt4(float4 v) {
    uint2 r;
    r.x = hpack(v.x, v.y);
    r.y = hpack(v.z, v.w);
    return r;
}
__device__ __forceinline__ void cpa16(uint32_t dst, const void* src) {
    asm volatile("cp.async.cg.shared.global [%0], [%1], 16;"
                 :: "r"(dst), "l"(src) : "memory");
}
__device__ __forceinline__ void cpa_commit() {
    asm volatile("cp.async.commit_group;" ::: "memory");
}
__device__ __forceinline__ void cpa_wait0() {
    asm volatile("cp.async.wait_group 0;" ::: "memory");
}

// ---------------- conversion kernels ------------------------------------------
__global__ void conv16_kernel(const float* __restrict__ s0,
                              const float* __restrict__ s1,
                              const float* __restrict__ s2, int n4) {
    int i = blockIdx.x * blockDim.x + threadIdx.x;
    if (i >= n4) return;
    int slot = blockIdx.y;
    const float* s = (slot == 0) ? s0 : (slot == 1 ? s1 : s2);
    float4 v = ((const float4*)s)[i];
    *(uint2*)(g_x16 + (size_t)slot * 4096 * 768 + (size_t)i * 4) = cvt4(v);
}

__global__ void transpose_conv_kernel(const float* __restrict__ W0,
                                      const float* __restrict__ W1,
                                      const float* __restrict__ W2,
                                      const float* __restrict__ W3) {
    __shared__ float t[32][33];
    int slot = blockIdx.z;
    const float* W = (slot == 0) ? W0 : (slot == 1) ? W1 : (slot == 2) ? W2 : W3;
    int tx = threadIdx.x, ty = threadIdx.y;
    int k = blockIdx.y * 32 + ty, n = blockIdx.x * 32 + tx;
    t[ty][tx] = W[(size_t)k * 768 + n];
    __syncthreads();
    int n2 = blockIdx.x * 32 + ty, k2 = blockIdx.y * 32 + tx;
    g_wt16[(size_t)slot * 768 * 768 + (size_t)n2 * 768 + k2] = __float2half(t[tx][ty]);
}

__global__ __launch_bounds__(256) void pbconv_kernel(const float* __restrict__ pb, int n4) {
    for (int i = blockIdx.x * blockDim.x + threadIdx.x; i < n4;
         i += gridDim.x * blockDim.x) {
        float4 v = ((const float4*)pb)[i];
        *(uint2*)(g_pb16 + (size_t)i * 4) = cvt4(v);
    }
}

// ---------------- HMMA dense GEMM (1 barrier / iter) ---------------------------
__device__ __forceinline__ void gemm_issue(uint32_t sbase, uint32_t bufoff,
        const __half* xx, const __half* wt, int bm, int bn, int k0, int tid) {
#pragma unroll
    for (int i = 0; i < 8; i++) {
        int idx = tid + i * 256;
        int bsel = idx >> 10, rc = idx & 1023;
        int row = rc >> 3, q = rc & 7;
        uint32_t dst = bufoff + (bsel ? 16384u : 0u) + SWZ(row * 128 + q * 16);
        const __half* src = bsel ? (wt + (size_t)(bn + row) * 768 + k0 + q * 8)
                                 : (xx + (size_t)(bm + row) * 768 + k0 + q * 8);
        cpa16(sbase + dst, src);
    }
    cpa_commit();
}

// mode 0: QKV (z=0/1/2; z==2 writes vw^T). mode 1: out projection (mhalf splits s).
__global__ __launch_bounds__(256) void gemm_mma_kernel(
    const float* __restrict__ b0, const float* __restrict__ b1,
    const float* __restrict__ b2, float* __restrict__ yout, int mode, int mhalf)
{
    extern __shared__ __align__(128) char smem[];
    const uint32_t sbase = smem_to_u32(smem);
    const int tid = threadIdx.x, wid = tid >> 5, lane = tid & 31;
    const int z = blockIdx.z;
    int bm;
    if (mode == 1) {
        int grp = blockIdx.y >> 2, off = blockIdx.y & 3;
        bm = (grp * 8 + off + mhalf * 4) * 128;
    } else {
        bm = blockIdx.y * 128;
    }
    const int bn = blockIdx.x * 128;
    const int xsel = (mode == 0) ? z : 0;
    const int wsel = (mode == 0) ? z : 3;
    const __half* xx = g_x16 + (size_t)xsel * 4096 * 768;
    const __half* wt = g_wt16 + (size_t)wsel * 768 * 768;
    const float* bias = (mode == 1) ? b0 : (z == 0 ? b0 : (z == 1 ? b1 : b2));

    const int wm = (wid >> 1) * 32, wn = (wid & 1) * 64;
    float acc[2][8][4];
#pragma unroll
    for (int a = 0; a < 2; a++)
#pragma unroll
        for (int b = 0; b < 8; b++)
#pragma unroll
            for (int c = 0; c < 4; c++) acc[a][b][c] = 0.f;

    gemm_issue(sbase, 0, xx, wt, bm, bn, 0, tid);
    for (int st = 0; st < 12; st++) {
        const int cur = st & 1;
        cpa_wait0();
        __syncthreads();
        if (st + 1 < 12)
            gemm_issue(sbase, (cur ^ 1) * 32768u, xx, wt, bm, bn, (st + 1) * 64, tid);
        const uint32_t Ac = cur * 32768u, Bc = Ac + 16384u;
#pragma unroll
        for (int kk = 0; kk < 4; kk++) {
            uint32_t a4[2][4];
            uint32_t aoff = SWZ((wm + (lane & 15)) * 128 + (kk * 2 + (lane >> 4)) * 16);
            ldmx4(a4[0], sbase + Ac + aoff);
            ldmx4(a4[1], sbase + Ac + aoff + 2048);
            uint32_t boff = SWZ((wn + (lane >> 4) * 8 + (lane & 7)) * 128 +
                                (kk * 2 + ((lane >> 3) & 1)) * 16);
#pragma unroll
            for (int ntp = 0; ntp < 4; ntp++) {
                uint32_t b4[4];
                ldmx4(b4, sbase + Bc + boff + ntp * 2048);
#pragma unroll
                for (int mt = 0; mt < 2; mt++) {
                    mmah(acc[mt][ntp * 2 + 0], a4[mt], b4);
                    mmah(acc[mt][ntp * 2 + 1], a4[mt], b4 + 2);
                }
            }
        }
    }

    if (mode == 0 && z == 2) {
        __syncthreads();                          // smem reuse as Th
        __half* Th = (__half*)smem;               // [128][136]
#pragma unroll
        for (int mt = 0; mt < 2; mt++) {
#pragma unroll
            for (int nt = 0; nt < 8; nt++) {
                int cl = wn + nt * 8 + (lane & 3) * 2;
                float bx = bias[bn + cl], by = bias[bn + cl + 1];
#pragma unroll
                for (int half = 0; half < 2; half++) {
                    int rl = wm + mt * 16 + (lane >> 2) + half * 8;
                    Th[cl * 136 + rl]       = __float2half(acc[mt][nt][half * 2 + 0] + bx);
                    Th[(cl + 1) * 136 + rl] = __float2half(acc[mt][nt][half * 2 + 1] + by);
                }
            }
        }
        __syncthreads();
        int b = bm >> 10, s0 = bm & 1023;
#pragma unroll
        for (int it = 0; it < 8; it++) {
            int g = tid + it * 256;
            int cl = g >> 4, q = g & 15;
            int cg = bn + cl, h = cg >> 6, d = cg & 63;
            size_t o = (((size_t)(b * Hh + h)) * 64 + d) * 1024 + s0 + q * 8;
            *(uint4*)(g_vwt16 + o) = *(uint4*)&Th[cl * 136 + q * 8];
        }
        return;
    }

#pragma unroll
    for (int mt = 0; mt < 2; mt++) {
#pragma unroll
        for (int nt = 0; nt < 8; nt++) {
            int col = bn + wn + nt * 8 + (lane & 3) * 2;
            float bx = bias[col], by = bias[col + 1];
#pragma unroll
            for (int half = 0; half < 2; half++) {
                int row = bm + wm + mt * 16 + (lane >> 2) + half * 8;
                float v0 = acc[mt][nt][half * 2 + 0] + bx;
                float v1 = acc[mt][nt][half * 2 + 1] + by;
                if (mode == 1) {
                    yout[(size_t)row * 768 + col]     = v0;
                    yout[(size_t)row * 768 + col + 1] = v1;
                } else {
                    int b = row >> 10, s = row & 1023;
                    int h = col >> 6, d = col & 63;
                    size_t base = ((size_t)(b * Hh + h) * S + s) * 64 + d;
                    __half* dstp = (z == 0) ? g_q16 : g_k16;
                    dstp[base]     = __float2half(v0);
                    dstp[base + 1] = __float2half(v1);
                }
            }
        }
    }
}

// ---------------- HMMA QK^T (writes fp16 scores) -------------------------------
__global__ __launch_bounds__(256) void qk_mma_kernel() {
    extern __shared__ __align__(128) char smem[];
    const uint32_t Ao = 0, Bo = 16384;
    const uint32_t sbase = smem_to_u32(smem);
    const int tid = threadIdx.x, wid = tid >> 5, lane = tid & 31;
    const int bh = blockIdx.z;
    const int bj = blockIdx.y * 128, bk = blockIdx.x * 128;
    const int wm = (wid >> 1) * 32, wn = (wid & 1) * 64;

    const size_t qb = ((size_t)bh * S + bj) * 64;
    const size_t kb = ((size_t)bh * S + bk) * 64;
#pragma unroll
    for (int i = 0; i < 8; i++) {
        int idx = tid + i * 256;
        int buf = idx >> 10, rc = idx & 1023;
        int row = rc >> 3, q = rc & 7;
        uint32_t dst = SWZ(row * 128 + q * 16);
        const __half* src = buf ? (g_k16 + kb + (size_t)row * 64 + q * 8)
                                : (g_q16 + qb + (size_t)row * 64 + q * 8);
        cpa16(sbase + (buf ? Bo : Ao) + dst, src);
    }
    cpa_commit();
    cpa_wait0();
    __syncthreads();

    float acc[2][8][4];
#pragma unroll
    for (int a = 0; a < 2; a++)
#pragma unroll
        for (int b = 0; b < 8; b++)
#pragma unroll
            for (int c = 0; c < 4; c++) acc[a][b][c] = 0.f;

#pragma unroll
    for (int kk = 0; kk < 4; kk++) {
        uint32_t a4[2][4];
        uint32_t aoff = SWZ((wm + (lane & 15)) * 128 + (kk * 2 + (lane >> 4)) * 16);
        ldmx4(a4[0], sbase + Ao + aoff);
        ldmx4(a4[1], sbase + Ao + aoff + 2048);
        uint32_t boff = SWZ((wn + (lane >> 4) * 8 + (lane & 7)) * 128 +
                            (kk * 2 + ((lane >> 3) & 1)) * 16);
#pragma unroll
        for (int ntp = 0; ntp < 4; ntp++) {
            uint32_t b4[4];
            ldmx4(b4, sbase + Bo + boff + ntp * 2048);
#pragma unroll
            for (int mt = 0; mt < 2; mt++) {
                mmah(acc[mt][ntp * 2 + 0], a4[mt], b4);
                mmah(acc[mt][ntp * 2 + 1], a4[mt], b4 + 2);
            }
        }
    }

#pragma unroll
    for (int mt = 0; mt < 2; mt++) {
#pragma unroll
        for (int nt = 0; nt < 8; nt++) {
            int col = bk + wn + nt * 8 + (lane & 3) * 2;
#pragma unroll
            for (int half = 0; half < 2; half++) {
                int row = bj + wm + mt * 16 + (lane >> 2) + half * 8;
                size_t idx = ((size_t)bh << 20) + ((size_t)row << 10) + col;
                *(uint32_t*)(g_s16 + idx) =
                    hpack(acc[mt][nt][half * 2 + 0], acc[mt][nt][half * 2 + 1]);
            }
        }
    }
}

// ---------------------------------------------------------------------------
// Fused: scores += qw·pb, scale+mask+softmax, A -> fp16, phase C attn = A·pb.
// Single barrier per chunk; AHc double-buffered. Grid (3, 512), j += joff.
// ---------------------------------------------------------------------------
__device__ __forceinline__ void pb_issue(uint32_t sbase, uint32_t off,
                                         int j, int k0, int tid) {
#pragma unroll
    for (int it = 0; it < 4; it++) {
        int idx = tid + it * 256;
        int kk = idx >> 3, q = idx & 7;
        cpa16(sbase + off + SWZ(kk * 128 + q * 16),
              g_pb16 + ((size_t)j * 1024 + k0 + kk) * 64 + q * 8);
    }
    cpa_commit();
}

__global__ __launch_bounds__(256) void fused_pbq_sm_kernel(
    const float* __restrict__ amask, const int* __restrict__ vmask, int joff)
{
    extern __shared__ __align__(128) char smem[];
    float* Sf = (float*)smem;                     // [16][1032] fp32 = 66048
    const uint32_t PB0 = 66048, PB1 = 82432;      // 2 x 16KB pb buffers
    const uint32_t QHo = 98816;                   // [16][64] fp16, 2KB
    float* AM = (float*)(smem + 100864);          // [1024] 4KB
    float* Mf = (float*)(smem + 104960);          // [2][1024] mask 8KB -> 113152
    const uint32_t AHc = 104960;                  // phase C: 2 x 4KB (reuses Mf)
    const uint32_t sbase = smem_to_u32(smem);
    const int tid = threadIdx.x, wid = tid >> 5, lane = tid & 31;
    const int t = blockIdx.x, j = blockIdx.y + joff;
    const int bh0 = t * 16, bmin = bh0 / Hh;

    pb_issue(sbase, PB0, j, 0, tid);

#pragma unroll
    for (int it = 0; it < 8; it++) {
        int idx = tid + it * 256;
        int row = idx >> 7, g = idx & 127;
        uint4 v = *(const uint4*)(g_s16 + (((size_t)(bh0 + row)) << 20) +
                                  ((size_t)j << 10) + g * 8);
        const __half2* hp = (const __half2*)&v;
        float2 f0 = __half22float2(hp[0]);
        float2 f1 = __half22float2(hp[1]);
        float2 f2 = __half22float2(hp[2]);
        float2 f3 = __half22float2(hp[3]);
        float* dstp = &Sf[row * 1032 + g * 8];
        dstp[0] = f0.x; dstp[1] = f0.y; dstp[2] = f1.x; dstp[3] = f1.y;
        dstp[4] = f2.x; dstp[5] = f2.y; dstp[6] = f3.x; dstp[7] = f3.y;
    }
    if (tid < 128) {
        int r = tid >> 3, q = tid & 7;
        uint32_t dst = SWZ(r * 128 + q * 16);
        size_t src = ((size_t)(bh0 + r) * 1024 + j) * 64 + q * 8;
        *(uint4*)(smem + QHo + dst) = *(const uint4*)(g_q16 + src);
    }
    *(float4*)&AM[tid * 4] = *(const float4*)(amask + (size_t)j * 1024 + tid * 4);
#pragma unroll
    for (int r2 = 0; r2 < 2; r2++) {
        int4 m = *(const int4*)(vmask + (size_t)(bmin + r2) * 1024 + tid * 4);
        Mf[r2 * 1024 + tid * 4 + 0] = m.x ? 1.f : 0.f;
        Mf[r2 * 1024 + tid * 4 + 1] = m.y ? 1.f : 0.f;
        Mf[r2 * 1024 + tid * 4 + 2] = m.z ? 1.f : 0.f;
        Mf[r2 * 1024 + tid * 4 + 3] = m.w ? 1.f : 0.f;
    }
    __syncthreads();

    uint32_t aq[4][4];
#pragma unroll
    for (int ks = 0; ks < 4; ks++) {
        uint32_t aoff = SWZ((lane & 15) * 128 + (ks * 2 + (lane >> 4)) * 16);
        ldmx4(aq[ks], sbase + QHo + aoff);
    }

    // ---- phase B (1 barrier/chunk) ----
    for (int c = 0; c < 8; c++) {
        const uint32_t cur = (c & 1) ? PB1 : PB0;
        cpa_wait0();
        __syncthreads();
        if (c + 1 < 8) pb_issue(sbase, (c & 1) ? PB0 : PB1, j, (c + 1) * 128, tid);
        const int k0 = c * 128;
        float frag[2][4] = {{0.f, 0.f, 0.f, 0.f}, {0.f, 0.f, 0.f, 0.f}};
#pragma unroll
        for (int ks = 0; ks < 4; ks++) {
            uint32_t boff = SWZ((wid * 16 + (lane >> 4) * 8 + (lane & 7)) * 128 +
                                (ks * 2 + ((lane >> 3) & 1)) * 16);
            uint32_t b4[4];
            ldmx4(b4, sbase + cur + boff);
            mmah(frag[0], aq[ks], b4);
            mmah(frag[1], aq[ks], b4 + 2);
        }
        int r0 = lane >> 2, c0 = (lane & 3) * 2;
#pragma unroll
        for (int nt = 0; nt < 2; nt++)
#pragma unroll
            for (int e = 0; e < 4; e++) {
                int row = r0 + (e >> 1) * 8;
                int col = k0 + wid * 16 + nt * 8 + c0 + (e & 1);
                Sf[row * 1032 + col] += frag[nt][e];
            }
    }
    __syncthreads();

    // ---- softmax ----
#pragma unroll
    for (int rr = 0; rr < 2; rr++) {
        int row = wid * 2 + rr;
        int bsel = (bh0 + row) / Hh - bmin;
        float x[32];
        float mx = -3.4e38f;
#pragma unroll
        for (int i = 0; i < 32; i++) {
            int k = lane + i * 32;
            float m = Mf[bsel * 1024 + k];
            float val = fmaf(Sf[row * 1032 + k], 0.125f, AM[k]);
            x[i] = (m != 0.f) ? val : NEGV;
            mx = fmaxf(mx, x[i]);
        }
#pragma unroll
        for (int o = 16; o > 0; o >>= 1) mx = fmaxf(mx, __shfl_xor_sync(~0u, mx, o));
        float sum = 0.f;
#pragma unroll
        for (int i = 0; i < 32; i++) { x[i] = __expf(x[i] - mx); sum += x[i]; }
#pragma unroll
        for (int o = 16; o > 0; o >>= 1) sum += __shfl_xor_sync(~0u, sum, o);
        float inv = 1.f / sum;
#pragma unroll
        for (int i = 0; i < 32; i++) Sf[row * 1032 + lane + i * 32] = x[i] * inv;
    }
    __syncthreads();

    pb_issue(sbase, PB0, j, 0, tid);

    // ---- write A fp16 ----
    {
        const int row = tid >> 4, kb = (tid & 15) * 64;
        const size_t obase = (((size_t)(bh0 + row)) << 20) + ((size_t)j << 10);
#pragma unroll
        for (int g = 0; g < 8; g++) {
            int k = kb + g * 8;
            uint2 p0 = cvt4(*(float4*)&Sf[row * 1032 + k]);
            uint2 p1 = cvt4(*(float4*)&Sf[row * 1032 + k + 4]);
            *(uint4*)(g_A16 + obase + k) = make_uint4(p0.x, p0.y, p1.x, p1.y);
        }
    }

    // ---- phase C (1 barrier/chunk, AHc double-buffered) ----
    float facc[4] = {0.f, 0.f, 0.f, 0.f};
    const int w16 = wid * 16;
    for (int c = 0; c < 8; c++) {
        const uint32_t cur = (c & 1) ? PB1 : PB0;
        const uint32_t ah = AHc + (uint32_t)(c & 1) * 4096u;
        const int k0 = c * 128;
        {
            int row = tid >> 4, col = (tid & 15) * 8;
            uint2 p0 = cvt4(*(float4*)&Sf[row * 1032 + k0 + col]);
            uint2 p1 = cvt4(*(float4*)&Sf[row * 1032 + k0 + col + 4]);
            uint32_t dst = SWZ256(row * 256 + col * 2);
            *(uint4*)(smem + ah + dst) = make_uint4(p0.x, p0.y, p1.x, p1.y);
        }
        cpa_wait0();
        __syncthreads();
        if (c + 1 < 8) pb_issue(sbase, (c & 1) ? PB0 : PB1, j, (c + 1) * 128, tid);
#pragma unroll
        for (int ks = 0; ks < 8; ks++) {
            uint32_t a4[4];
            uint32_t aoff = SWZ256((lane & 15) * 256 + (ks * 2 + (lane >> 4)) * 16);
            ldmx4(a4, sbase + ah + aoff);
            uint32_t bt[2];
            uint32_t boff = SWZ((ks * 16 + (lane & 15)) * 128 + w16);
            ldmx2t(bt, sbase + cur + boff);
            mmah(facc, a4, bt);
        }
    }
    {
        int d = wid * 8 + (lane & 3) * 2;
#pragma unroll
        for (int half = 0; half < 2; half++) {
            int bh = bh0 + (lane >> 2) + half * 8;
            int b = bh / Hh, h = bh % Hh;
            size_t o = ((size_t)(b * 1024 + j)) * 768 + h * 64 + d;
            g_attn[o]     = facc[half * 2 + 0];
            g_attn[o + 1] = facc[half * 2 + 1];
        }
    }
}

// ---------------------------------------------------------------------------
// av: x16[0] = fp16(attn_pb + A·vw). Grid (4, 48), jtile = blockIdx.x + x0.
// ---------------------------------------------------------------------------
__device__ __forceinline__ void av_issue(uint32_t sbase, uint32_t bufoff,
                                         int bh, int j0, int k0, int tid) {
#pragma unroll
    for (int it = 0; it < 12; it++) {
        int idx = tid + it * 256;
        if (idx < 2048) {
            int row = idx >> 4, q = idx & 15;
            cpa16(sbase + bufoff + SWZ256(row * 256 + q * 16),
                  g_A16 + (((size_t)bh) << 20) +
                  ((size_t)(j0 + row) << 10) + k0 + q * 8);
        } else {
            int rc = idx - 2048;
            int d = rc >> 4, q = rc & 15;
            cpa16(sbase + bufoff + 32768u + SWZ256(d * 256 + q * 16),
                  g_vwt16 + ((size_t)bh * 64 + d) * 1024 + k0 + q * 8);
        }
    }
    cpa_commit();
}

__global__ __launch_bounds__(256) void av_mma_kernel(int x0) {
    extern __shared__ __align__(128) char smem[];
    const uint32_t sbase = smem_to_u32(smem);
    const int tid = threadIdx.x, wid = tid >> 5, lane = tid & 31;
    const int bh = blockIdx.y, j0 = (blockIdx.x + x0) * 128;

    float facc[8][4];
#pragma unroll
    for (int a = 0; a < 8; a++)
#pragma unroll
        for (int b = 0; b < 4; b++) facc[a][b] = 0.f;

    av_issue(sbase, 0, bh, j0, 0, tid);
    for (int c = 0; c < 8; c++) {
        const uint32_t cur = (c & 1) * 49152u;
        cpa_wait0();
        __syncthreads();
        if (c + 1 < 8)
            av_issue(sbase, ((c & 1) ^ 1) * 49152u, bh, j0, (c + 1) * 128, tid);
        const uint32_t Ac = cur, Vc = cur + 32768u;
#pragma unroll
        for (int ks = 0; ks < 8; ks++) {
            uint32_t a4[4];
            uint32_t aoff = SWZ256((wid * 16 + (lane & 15)) * 256 +
                                   (ks * 2 + (lane >> 4)) * 16);
            ldmx4(a4, sbase + Ac + aoff);
#pragma unroll
            for (int np = 0; np < 4; np++) {
                uint32_t boff = SWZ256((np * 16 + (lane >> 4) * 8 + (lane & 7)) * 256 +
                                       (ks * 2 + ((lane >> 3) & 1)) * 16);
                uint32_t b4[4];
                ldmx4(b4, sbase + Vc + boff);
                mmah(facc[np * 2 + 0], a4, b4);
                mmah(facc[np * 2 + 1], a4, b4 + 2);
            }
        }
    }
    const int b = bh / Hh, h = bh % Hh;
#pragma unroll
    for (int nt = 0; nt < 8; nt++) {
        int d = nt * 8 + (lane & 3) * 2;
#pragma unroll
        for (int half = 0; half < 2; half++) {
            int s = j0 + wid * 16 + (lane >> 2) + half * 8;
            size_t o = ((size_t)(b * 1024 + s)) * 768 + h * 64 + d;
            float v0 = g_attn[o]     + facc[nt][half * 2 + 0];
            float v1 = g_attn[o + 1] + facc[nt][half * 2 + 1];
            *(uint32_t*)(g_x16 + o) = hpack(v0, v1);
        }
    }
}

// ---------------------------------------------------------------------------
extern "C" void kernel_launch(void* const* d_in, const int* in_sizes, int n_in,
                              void* d_out, int out_size) {
    const float* q     = (const float*)d_in[0];
    const float* k     = (const float*)d_in[1];
    const float* v     = (const float*)d_in[2];
    const float* amask = (const float*)d_in[3];
    const float* pb    = (const float*)d_in[4];
    const int*   vmask = (const int*)  d_in[5];
    const float* Wq    = (const float*)d_in[6];
    const float* bq    = (const float*)d_in[7];
    const float* Wk    = (const float*)d_in[8];
    const float* bk    = (const float*)d_in[9];
    const float* Wv    = (const float*)d_in[10];
    const float* bv    = (const float*)d_in[11];
    const float* Wo    = (const float*)d_in[12];
    const float* bo    = (const float*)d_in[13];
    float* out = (float*)d_out;

    const int SM_GEMM = 65536, SM_QK = 32768, SM_FUSED = 113152, SM_AV = 98304;
    static cudaStream_t s1;
    static cudaEvent_t ev_fork, ev_join, ev_f1, ev_av1, ev_op1;
    static bool attr_done = false;
    if (!attr_done) {
        cudaFuncSetAttribute(gemm_mma_kernel, cudaFuncAttributeMaxDynamicSharedMemorySize, SM_GEMM);
        cudaFuncSetAttribute(qk_mma_kernel, cudaFuncAttributeMaxDynamicSharedMemorySize, SM_QK);
        cudaFuncSetAttribute(fused_pbq_sm_kernel, cudaFuncAttributeMaxDynamicSharedMemorySize, SM_FUSED);
        cudaFuncSetAttribute(av_mma_kernel, cudaFuncAttributeMaxDynamicSharedMemorySize, SM_AV);
        cudaStreamCreateWithFlags(&s1, cudaStreamNonBlocking);
        cudaEventCreateWithFlags(&ev_fork, cudaEventDisableTiming);
        cudaEventCreateWithFlags(&ev_join, cudaEventDisableTiming);
        cudaEventCreateWithFlags(&ev_f1, cudaEventDisableTiming);
        cudaEventCreateWithFlags(&ev_av1, cudaEventDisableTiming);
        cudaEventCreateWithFlags(&ev_op1, cudaEventDisableTiming);
        attr_done = true;
    }

    const int n4 = 4096 * 768 / 4;
    const int pb4 = 1024 * 1024 * 64 / 4;

    // fork: pbconv (grid-stride) overlaps the projection chain
    cudaEventRecord(ev_fork, (cudaStream_t)0);
    cudaStreamWaitEvent(s1, ev_fork, 0);
    pbconv_kernel<<<512, 256, 0, s1>>>(pb, pb4);
    cudaEventRecord(ev_join, s1);

    conv16_kernel<<<dim3(n4 / 256, 3), 256>>>(q, k, v, n4);
    dim3 tthr(32, 32), tgrd(24, 24, 4);
    transpose_conv_kernel<<<tgrd, tthr>>>(Wq, Wk, Wv, Wo);
    gemm_mma_kernel<<<dim3(6, 32, 3), 256, SM_GEMM>>>(bq, bk, bv, nullptr, 0, 0);
    qk_mma_kernel<<<dim3(8, 8, 48), 256, SM_QK>>>();

    // join: fused needs pb16
    cudaStreamWaitEvent((cudaStream_t)0, ev_join, 0);
    fused_pbq_sm_kernel<<<dim3(3, 512), 256, SM_FUSED>>>(amask, vmask, 0);
    cudaEventRecord(ev_f1, (cudaStream_t)0);
    fused_pbq_sm_kernel<<<dim3(3, 512), 256, SM_FUSED>>>(amask, vmask, 512);

    // av half 1 (+ out-proj half 1) on side stream, overlapped with fused half 2
    cudaStreamWaitEvent(s1, ev_f1, 0);
    av_mma_kernel<<<dim3(4, 48), 256, SM_AV, s1>>>(0);
    cudaEventRecord(ev_av1, s1);
    gemm_mma_kernel<<<dim3(6, 16, 1), 256, SM_GEMM, s1>>>(bo, nullptr, nullptr, out, 1, 0);
    cudaEventRecord(ev_op1, s1);

    // av half 2 + out-proj half 2 on main stream
    av_mma_kernel<<<dim3(4, 48), 256, SM_AV>>>(4);
    cudaStreamWaitEvent((cudaStream_t)0, ev_av1, 0);
    gemm_mma_kernel<<<dim3(6, 16, 1), 256, SM_GEMM>>>(bo, nullptr, nullptr, out, 1, 1);
    cudaStreamWaitEvent((cudaStream_t)0, ev_op1, 0);
}

// round 15
// speedup vs baseline: 1.1624x; 1.1624x over previous
#include <cuda_runtime.h>
#include <cuda_fp16.h>
#include <cstdint>

// ---------------------------------------------------------------------------
// NEZHA-style MHA, all single-fp16 HMMA, cp.async double-buffered mainloops,
// fp16 scores; fused kernel: 48 bh rows per j-block, fp16 smem scores.
// B=4, S=1024, H=12, DK=DV=64, DM=768.
// ---------------------------------------------------------------------------

#define S 1024
#define Hh 12
#define BH 48
#define NEGV (-1e12f)

// ---------------- scratch -----------------------------------------------------
__device__ float g_attn[(size_t)4 * S * 768];

__device__ __align__(16) __half g_s16[(size_t)BH * S * S];      // scores, 100 MB
__device__ __align__(16) __half g_x16[(size_t)3 * 4096 * 768];
__device__ __align__(16) __half g_wt16[(size_t)4 * 768 * 768];
__device__ __align__(16) __half g_q16[(size_t)BH * S * 64];
__device__ __align__(16) __half g_k16[(size_t)BH * S * 64];
__device__ __align__(16) __half g_vwt16[(size_t)BH * 64 * S];   // [bh][d][s]
__device__ __align__(16) __half g_A16[(size_t)BH * S * S];      // 100 MB
__device__ __align__(16) __half g_pb16[(size_t)S * S * 64];     // [j][k][d] 128MB

// ---------------- helpers -----------------------------------------------------
__device__ __forceinline__ uint32_t smem_to_u32(const void* p) {
    uint32_t a;
    asm("{ .reg .u64 t; cvta.to.shared.u64 t, %1; cvt.u32.u64 %0, t; }"
        : "=r"(a) : "l"(p));
    return a;
}
#define SWZ(o)    ((uint32_t)(o) ^ ((((uint32_t)(o)) >> 3) & 0x70))
#define SWZ256(o) ((uint32_t)(o) ^ ((((uint32_t)(o)) >> 4) & 0x70))

__device__ __forceinline__ void ldmx4(uint32_t* r, uint32_t a) {
    asm volatile("ldmatrix.sync.aligned.m8n8.x4.shared.b16 {%0,%1,%2,%3}, [%4];"
                 : "=r"(r[0]), "=r"(r[1]), "=r"(r[2]), "=r"(r[3]) : "r"(a));
}
__device__ __forceinline__ void ldmx2t(uint32_t* r, uint32_t a) {
    asm volatile("ldmatrix.sync.aligned.m8n8.x2.trans.shared.b16 {%0,%1}, [%2];"
                 : "=r"(r[0]), "=r"(r[1]) : "r"(a));
}
__device__ __forceinline__ void mmah(float* c, const uint32_t* a,
                                     const uint32_t* b) {
    asm volatile(
        "mma.sync.aligned.m16n8k16.row.col.f32.f16.f16.f32 "
        "{%0,%1,%2,%3},{%4,%5,%6,%7},{%8,%9},{%0,%1,%2,%3};"
        : "+f"(c[0]), "+f"(c[1]), "+f"(c[2]), "+f"(c[3])
        : "r"(a[0]), "r"(a[1]), "r"(a[2]), "r"(a[3]), "r"(b[0]), "r"(b[1]));
}
__device__ __forceinline__ uint32_t hpack(float a, float b) {
    __half2 t = __floats2half2_rn(a, b);
    return *(uint32_t*)&t;
}
__device__ __forceinline__ uint2 cvt4(float4 v) {
    uint2 r;
    r.x = hpack(v.x, v.y);
    r.y = hpack(v.z, v.w);
    return r;
}
__device__ __forceinline__ void cpa16(uint32_t dst, const void* src) {
    asm volatile("cp.async.cg.shared.global [%0], [%1], 16;"
                 :: "r"(dst), "l"(src) : "memory");
}
__device__ __forceinline__ void cpa_commit() {
    asm volatile("cp.async.commit_group;" ::: "memory");
}
__device__ __forceinline__ void cpa_wait0() {
    asm volatile("cp.async.wait_group 0;" ::: "memory");
}
__device__ __forceinline__ void cpa_wait1() {
    asm volatile("cp.async.wait_group 1;" ::: "memory");
}

// ---------------- conversion kernels ------------------------------------------
__global__ void conv16_kernel(const float* __restrict__ s0,
                              const float* __restrict__ s1,
                              const float* __restrict__ s2, int n4) {
    int i = blockIdx.x * blockDim.x + threadIdx.x;
    if (i >= n4) return;
    int slot = blockIdx.y;
    const float* s = (slot == 0) ? s0 : (slot == 1 ? s1 : s2);
    float4 v = ((const float4*)s)[i];
    *(uint2*)(g_x16 + (size_t)slot * 4096 * 768 + (size_t)i * 4) = cvt4(v);
}

__global__ void transpose_conv_kernel(const float* __restrict__ W0,
                                      const float* __restrict__ W1,
                                      const float* __restrict__ W2,
                                      const float* __restrict__ W3) {
    __shared__ float t[32][33];
    int slot = blockIdx.z;
    const float* W = (slot == 0) ? W0 : (slot == 1) ? W1 : (slot == 2) ? W2 : W3;
    int tx = threadIdx.x, ty = threadIdx.y;
    int k = blockIdx.y * 32 + ty, n = blockIdx.x * 32 + tx;
    t[ty][tx] = W[(size_t)k * 768 + n];
    __syncthreads();
    int n2 = blockIdx.x * 32 + ty, k2 = blockIdx.y * 32 + tx;
    g_wt16[(size_t)slot * 768 * 768 + (size_t)n2 * 768 + k2] = __float2half(t[tx][ty]);
}

__global__ __launch_bounds__(256) void pbconv_kernel(const float* __restrict__ pb, int n4) {
    for (int i = blockIdx.x * blockDim.x + threadIdx.x; i < n4;
         i += gridDim.x * blockDim.x) {
        float4 v = ((const float4*)pb)[i];
        *(uint2*)(g_pb16 + (size_t)i * 4) = cvt4(v);
    }
}

// ---------------- HMMA dense GEMM (R13 structure) ------------------------------
__device__ __forceinline__ void gemm_issue(uint32_t sbase, uint32_t bufoff,
        const __half* xx, const __half* wt, int bm, int bn, int k0, int tid) {
#pragma unroll
    for (int i = 0; i < 8; i++) {
        int idx = tid + i * 256;
        int bsel = idx >> 10, rc = idx & 1023;
        int row = rc >> 3, q = rc & 7;
        uint32_t dst = bufoff + (bsel ? 16384u : 0u) + SWZ(row * 128 + q * 16);
        const __half* src = bsel ? (wt + (size_t)(bn + row) * 768 + k0 + q * 8)
                                 : (xx + (size_t)(bm + row) * 768 + k0 + q * 8);
        cpa16(sbase + dst, src);
    }
    cpa_commit();
}

__global__ __launch_bounds__(256) void gemm_mma_kernel(
    const float* __restrict__ b0, const float* __restrict__ b1,
    const float* __restrict__ b2, float* __restrict__ yout, int mode)
{
    extern __shared__ __align__(128) char smem[];
    const uint32_t sbase = smem_to_u32(smem);
    const int tid = threadIdx.x, wid = tid >> 5, lane = tid & 31;
    const int z = blockIdx.z;
    const int bm = blockIdx.y * 128, bn = blockIdx.x * 128;
    const int xsel = (mode == 0) ? z : 0;
    const int wsel = (mode == 0) ? z : 3;
    const __half* xx = g_x16 + (size_t)xsel * 4096 * 768;
    const __half* wt = g_wt16 + (size_t)wsel * 768 * 768;
    const float* bias = (mode == 1) ? b0 : (z == 0 ? b0 : (z == 1 ? b1 : b2));

    const int wm = (wid >> 1) * 32, wn = (wid & 1) * 64;
    float acc[2][8][4];
#pragma unroll
    for (int a = 0; a < 2; a++)
#pragma unroll
        for (int b = 0; b < 8; b++)
#pragma unroll
            for (int c = 0; c < 4; c++) acc[a][b][c] = 0.f;

    gemm_issue(sbase, 0, xx, wt, bm, bn, 0, tid);
    for (int st = 0; st < 12; st++) {
        const int cur = st & 1;
        if (st + 1 < 12) {
            gemm_issue(sbase, (cur ^ 1) * 32768u, xx, wt, bm, bn, (st + 1) * 64, tid);
            cpa_wait1();
        } else {
            cpa_wait0();
        }
        __syncthreads();
        const uint32_t Ac = cur * 32768u, Bc = Ac + 16384u;
#pragma unroll
        for (int kk = 0; kk < 4; kk++) {
            uint32_t a4[2][4];
            uint32_t aoff = SWZ((wm + (lane & 15)) * 128 + (kk * 2 + (lane >> 4)) * 16);
            ldmx4(a4[0], sbase + Ac + aoff);
            ldmx4(a4[1], sbase + Ac + aoff + 2048);
            uint32_t boff = SWZ((wn + (lane >> 4) * 8 + (lane & 7)) * 128 +
                                (kk * 2 + ((lane >> 3) & 1)) * 16);
#pragma unroll
            for (int ntp = 0; ntp < 4; ntp++) {
                uint32_t b4[4];
                ldmx4(b4, sbase + Bc + boff + ntp * 2048);
#pragma unroll
                for (int mt = 0; mt < 2; mt++) {
                    mmah(acc[mt][ntp * 2 + 0], a4[mt], b4);
                    mmah(acc[mt][ntp * 2 + 1], a4[mt], b4 + 2);
                }
            }
        }
        __syncthreads();
    }

    if (mode == 0 && z == 2) {
        __half* Th = (__half*)smem;               // [128][136]
#pragma unroll
        for (int mt = 0; mt < 2; mt++) {
#pragma unroll
            for (int nt = 0; nt < 8; nt++) {
                int cl = wn + nt * 8 + (lane & 3) * 2;
                float bx = bias[bn + cl], by = bias[bn + cl + 1];
#pragma unroll
                for (int half = 0; half < 2; half++) {
                    int rl = wm + mt * 16 + (lane >> 2) + half * 8;
                    Th[cl * 136 + rl]       = __float2half(acc[mt][nt][half * 2 + 0] + bx);
                    Th[(cl + 1) * 136 + rl] = __float2half(acc[mt][nt][half * 2 + 1] + by);
                }
            }
        }
        __syncthreads();
        int b = bm >> 10, s0 = bm & 1023;
#pragma unroll
        for (int it = 0; it < 8; it++) {
            int g = tid + it * 256;
            int cl = g >> 4, q = g & 15;
            int cg = bn + cl, h = cg >> 6, d = cg & 63;
            size_t o = (((size_t)(b * Hh + h)) * 64 + d) * 1024 + s0 + q * 8;
            *(uint4*)(g_vwt16 + o) = *(uint4*)&Th[cl * 136 + q * 8];
        }
        return;
    }

#pragma unroll
    for (int mt = 0; mt < 2; mt++) {
#pragma unroll
        for (int nt = 0; nt < 8; nt++) {
            int col = bn + wn + nt * 8 + (lane & 3) * 2;
            float bx = bias[col], by = bias[col + 1];
#pragma unroll
            for (int half = 0; half < 2; half++) {
                int row = bm + wm + mt * 16 + (lane >> 2) + half * 8;
                float v0 = acc[mt][nt][half * 2 + 0] + bx;
                float v1 = acc[mt][nt][half * 2 + 1] + by;
                if (mode == 1) {
                    yout[(size_t)row * 768 + col]     = v0;
                    yout[(size_t)row * 768 + col + 1] = v1;
                } else {
                    int b = row >> 10, s = row & 1023;
                    int h = col >> 6, d = col & 63;
                    size_t base = ((size_t)(b * Hh + h) * S + s) * 64 + d;
                    __half* dstp = (z == 0) ? g_q16 : g_k16;
                    dstp[base]     = __float2half(v0);
                    dstp[base + 1] = __float2half(v1);
                }
            }
        }
    }
}

// ---------------- HMMA QK^T (writes fp16 scores) -------------------------------
__global__ __launch_bounds__(256) void qk_mma_kernel() {
    extern __shared__ __align__(128) char smem[];
    const uint32_t Ao = 0, Bo = 16384;
    const uint32_t sbase = smem_to_u32(smem);
    const int tid = threadIdx.x, wid = tid >> 5, lane = tid & 31;
    const int bh = blockIdx.z;
    const int bj = blockIdx.y * 128, bk = blockIdx.x * 128;
    const int wm = (wid >> 1) * 32, wn = (wid & 1) * 64;

    const size_t qb = ((size_t)bh * S + bj) * 64;
    const size_t kb = ((size_t)bh * S + bk) * 64;
#pragma unroll
    for (int i = 0; i < 8; i++) {
        int idx = tid + i * 256;
        int buf = idx >> 10, rc = idx & 1023;
        int row = rc >> 3, q = rc & 7;
        uint32_t dst = SWZ(row * 128 + q * 16);
        const __half* src = buf ? (g_k16 + kb + (size_t)row * 64 + q * 8)
                                : (g_q16 + qb + (size_t)row * 64 + q * 8);
        cpa16(sbase + (buf ? Bo : Ao) + dst, src);
    }
    cpa_commit();
    cpa_wait0();
    __syncthreads();

    float acc[2][8][4];
#pragma unroll
    for (int a = 0; a < 2; a++)
#pragma unroll
        for (int b = 0; b < 8; b++)
#pragma unroll
            for (int c = 0; c < 4; c++) acc[a][b][c] = 0.f;

#pragma unroll
    for (int kk = 0; kk < 4; kk++) {
        uint32_t a4[2][4];
        uint32_t aoff = SWZ((wm + (lane & 15)) * 128 + (kk * 2 + (lane >> 4)) * 16);
        ldmx4(a4[0], sbase + Ao + aoff);
        ldmx4(a4[1], sbase + Ao + aoff + 2048);
        uint32_t boff = SWZ((wn + (lane >> 4) * 8 + (lane & 7)) * 128 +
                            (kk * 2 + ((lane >> 3) & 1)) * 16);
#pragma unroll
        for (int ntp = 0; ntp < 4; ntp++) {
            uint32_t b4[4];
            ldmx4(b4, sbase + Bo + boff + ntp * 2048);
#pragma unroll
            for (int mt = 0; mt < 2; mt++) {
                mmah(acc[mt][ntp * 2 + 0], a4[mt], b4);
                mmah(acc[mt][ntp * 2 + 1], a4[mt], b4 + 2);
            }
        }
    }

#pragma unroll
    for (int mt = 0; mt < 2; mt++) {
#pragma unroll
        for (int nt = 0; nt < 8; nt++) {
            int col = bk + wn + nt * 8 + (lane & 3) * 2;
#pragma unroll
            for (int half = 0; half < 2; half++) {
                int row = bj + wm + mt * 16 + (lane >> 2) + half * 8;
                size_t idx = ((size_t)bh << 20) + ((size_t)row << 10) + col;
                *(uint32_t*)(g_s16 + idx) =
                    hpack(acc[mt][nt][half * 2 + 0], acc[mt][nt][half * 2 + 1]);
            }
        }
    }
}

// ---------------------------------------------------------------------------
// fused48: one block per j covers ALL 48 bh. S16[48][1032] fp16 smem scores.
// Phase B: S16 += qw·pb; softmax; A write; phase C: attn = A·pb.
// Grid (512), j = blockIdx.x + joff, 256 threads, smem 170752.
// ---------------------------------------------------------------------------
__device__ __forceinline__ void pb_issue(uint32_t sbase, uint32_t off,
                                         int j, int k0, int tid) {
#pragma unroll
    for (int it = 0; it < 4; it++) {
        int idx = tid + it * 256;
        int kk = idx >> 3, q = idx & 7;
        cpa16(sbase + off + SWZ(kk * 128 + q * 16),
              g_pb16 + ((size_t)j * 1024 + k0 + kk) * 64 + q * 8);
    }
    cpa_commit();
}

__global__ __launch_bounds__(256) void fused48_kernel(
    const float* __restrict__ amask, const int* __restrict__ vmask, int joff)
{
    extern __shared__ __align__(128) char smem[];
    __half* S16 = (__half*)smem;                  // [48][1032] = 99072
    const uint32_t PB0 = 99072, PB1 = 115456;     // 2 x 16KB pb buffers
    const uint32_t QHo = 131840;                  // [48][128B] swizzled, 6144
    float* AM = (float*)(smem + 137984);          // [1024] 4KB
    float* Mf = (float*)(smem + 142080);          // [4][1024] 16KB
    const uint32_t AHc = 158464;                  // [48][256B] SWZ256, 12288
    const uint32_t sbase = smem_to_u32(smem);
    const int tid = threadIdx.x, wid = tid >> 5, lane = tid & 31;
    const int j = blockIdx.x + joff;

    pb_issue(sbase, PB0, j, 0, tid);

    // load scores (48 rows x 1024 halves)
#pragma unroll
    for (int it = 0; it < 24; it++) {
        int idx = tid + it * 256;
        int row = idx >> 7, g = idx & 127;
        *(uint4*)&S16[row * 1032 + g * 8] =
            *(const uint4*)(g_s16 + (((size_t)row) << 20) +
                            ((size_t)j << 10) + g * 8);
    }
    // Q: 48 rows x 64 halves, swizzled
#pragma unroll
    for (int it = 0; it < 2; it++) {
        int idx = tid + it * 256;
        if (idx < 384) {
            int r = idx >> 3, q = idx & 7;
            uint32_t dst = SWZ(r * 128 + q * 16);
            *(uint4*)(smem + QHo + dst) =
                *(const uint4*)(g_q16 + ((size_t)r * 1024 + j) * 64 + q * 8);
        }
    }
    *(float4*)&AM[tid * 4] = *(const float4*)(amask + (size_t)j * 1024 + tid * 4);
#pragma unroll
    for (int r2 = 0; r2 < 4; r2++) {
        int4 m = *(const int4*)(vmask + (size_t)r2 * 1024 + tid * 4);
        Mf[r2 * 1024 + tid * 4 + 0] = m.x ? 1.f : 0.f;
        Mf[r2 * 1024 + tid * 4 + 1] = m.y ? 1.f : 0.f;
        Mf[r2 * 1024 + tid * 4 + 2] = m.z ? 1.f : 0.f;
        Mf[r2 * 1024 + tid * 4 + 3] = m.w ? 1.f : 0.f;
    }
    __syncthreads();

    // ---- phase B: S16 += qw·pb ----
    for (int c = 0; c < 8; c++) {
        const uint32_t cur = (c & 1) ? PB1 : PB0;
        if (c + 1 < 8) {
            pb_issue(sbase, (c & 1) ? PB0 : PB1, j, (c + 1) * 128, tid);
            cpa_wait1();
        } else {
            cpa_wait0();
        }
        __syncthreads();
        const int k0 = c * 128;
        float frag[3][2][4];
#pragma unroll
        for (int mt = 0; mt < 3; mt++)
#pragma unroll
            for (int nt = 0; nt < 2; nt++)
#pragma unroll
                for (int e = 0; e < 4; e++) frag[mt][nt][e] = 0.f;
#pragma unroll
        for (int ks = 0; ks < 4; ks++) {
            uint32_t boff = SWZ((wid * 16 + (lane >> 4) * 8 + (lane & 7)) * 128 +
                                (ks * 2 + ((lane >> 3) & 1)) * 16);
            uint32_t b4[4];
            ldmx4(b4, sbase + cur + boff);
#pragma unroll
            for (int mt = 0; mt < 3; mt++) {
                uint32_t a4[4];
                uint32_t aoff = SWZ((mt * 16 + (lane & 15)) * 128 +
                                    (ks * 2 + (lane >> 4)) * 16);
                ldmx4(a4, sbase + QHo + aoff);
                mmah(frag[mt][0], a4, b4);
                mmah(frag[mt][1], a4, b4 + 2);
            }
        }
        const int r0 = lane >> 2, c0 = (lane & 3) * 2;
#pragma unroll
        for (int mt = 0; mt < 3; mt++)
#pragma unroll
            for (int nt = 0; nt < 2; nt++)
#pragma unroll
                for (int eh = 0; eh < 2; eh++) {
                    int row = mt * 16 + r0 + eh * 8;
                    int col = k0 + wid * 16 + nt * 8 + c0;
                    __half2* p = (__half2*)&S16[row * 1032 + col];
                    float2 old = __half22float2(*p);
                    *p = __floats2half2_rn(old.x + frag[mt][nt][eh * 2 + 0],
                                           old.y + frag[mt][nt][eh * 2 + 1]);
                }
        __syncthreads();
    }

    // ---- softmax: warp w handles rows w*6 .. w*6+5 ----
#pragma unroll
    for (int rr = 0; rr < 6; rr++) {
        int row = wid * 6 + rr;
        int bsel = row / Hh;
        float x[32];
        float mx = -3.4e38f;
#pragma unroll
        for (int i = 0; i < 32; i++) {
            int k = lane + i * 32;
            float m = Mf[bsel * 1024 + k];
            float val = fmaf(__half2float(S16[row * 1032 + k]), 0.125f, AM[k]);
            x[i] = (m != 0.f) ? val : NEGV;
            mx = fmaxf(mx, x[i]);
        }
#pragma unroll
        for (int o = 16; o > 0; o >>= 1) mx = fmaxf(mx, __shfl_xor_sync(~0u, mx, o));
        float sum = 0.f;
#pragma unroll
        for (int i = 0; i < 32; i++) { x[i] = __expf(x[i] - mx); sum += x[i]; }
#pragma unroll
        for (int o = 16; o > 0; o >>= 1) sum += __shfl_xor_sync(~0u, sum, o);
        float inv = 1.f / sum;
#pragma unroll
        for (int i = 0; i < 32; i++)
            S16[row * 1032 + lane + i * 32] = __float2half(x[i] * inv);
    }
    __syncthreads();

    pb_issue(sbase, PB0, j, 0, tid);

    // ---- write A fp16 (straight copy of S16) ----
#pragma unroll
    for (int it = 0; it < 24; it++) {
        int idx = tid + it * 256;
        int row = idx >> 7, g = idx & 127;
        *(uint4*)(g_A16 + (((size_t)row) << 20) + ((size_t)j << 10) + g * 8) =
            *(uint4*)&S16[row * 1032 + g * 8];
    }

    // ---- phase C: attn[0..47][d] = A·pb ----
    float facc[3][4];
#pragma unroll
    for (int mt = 0; mt < 3; mt++)
#pragma unroll
        for (int e = 0; e < 4; e++) facc[mt][e] = 0.f;
    const int w16 = wid * 16;
    for (int c = 0; c < 8; c++) {
        const uint32_t cur = (c & 1) ? PB1 : PB0;
        const int k0 = c * 128;
        // stage A chunk into AHc (48 x 128 halves, SWZ256)
#pragma unroll
        for (int it = 0; it < 3; it++) {
            int idx = tid + it * 256;
            int row = idx >> 4, q = idx & 15;
            uint32_t dst = SWZ256(row * 256 + q * 16);
            *(uint4*)(smem + AHc + dst) = *(uint4*)&S16[row * 1032 + k0 + q * 8];
        }
        if (c + 1 < 8) {
            pb_issue(sbase, (c & 1) ? PB0 : PB1, j, (c + 1) * 128, tid);
            cpa_wait1();
        } else {
            cpa_wait0();
        }
        __syncthreads();
#pragma unroll
        for (int ks = 0; ks < 8; ks++) {
            uint32_t bt[2];
            uint32_t boff = SWZ((ks * 16 + (lane & 15)) * 128 + w16);
            ldmx2t(bt, sbase + cur + boff);
#pragma unroll
            for (int mt = 0; mt < 3; mt++) {
                uint32_t a4[4];
                uint32_t aoff = SWZ256((mt * 16 + (lane & 15)) * 256 +
                                       (ks * 2 + (lane >> 4)) * 16);
                ldmx4(a4, sbase + AHc + aoff);
                mmah(facc[mt], a4, bt);
            }
        }
        __syncthreads();
    }
    {
        int d = wid * 8 + (lane & 3) * 2;
#pragma unroll
        for (int mt = 0; mt < 3; mt++)
#pragma unroll
            for (int half = 0; half < 2; half++) {
                int bh = mt * 16 + (lane >> 2) + half * 8;
                int b = bh / Hh, h = bh % Hh;
                size_t o = ((size_t)(b * 1024 + j)) * 768 + h * 64 + d;
                g_attn[o]     = facc[mt][half * 2 + 0];
                g_attn[o + 1] = facc[mt][half * 2 + 1];
            }
    }
}

// ---------------------------------------------------------------------------
// av: x16[0] = fp16(attn_pb + A·vw). Grid (4, 48), jtile = blockIdx.x + x0.
// ---------------------------------------------------------------------------
__device__ __forceinline__ void av_issue(uint32_t sbase, uint32_t bufoff,
                                         int bh, int j0, int k0, int tid) {
#pragma unroll
    for (int it = 0; it < 12; it++) {
        int idx = tid + it * 256;
        if (idx < 2048) {
            int row = idx >> 4, q = idx & 15;
            cpa16(sbase + bufoff + SWZ256(row * 256 + q * 16),
                  g_A16 + (((size_t)bh) << 20) +
                  ((size_t)(j0 + row) << 10) + k0 + q * 8);
        } else {
            int rc = idx - 2048;
            int d = rc >> 4, q = rc & 15;
            cpa16(sbase + bufoff + 32768u + SWZ256(d * 256 + q * 16),
                  g_vwt16 + ((size_t)bh * 64 + d) * 1024 + k0 + q * 8);
        }
    }
    cpa_commit();
}

__global__ __launch_bounds__(256) void av_mma_kernel(int x0) {
    extern __shared__ __align__(128) char smem[];
    const uint32_t sbase = smem_to_u32(smem);
    const int tid = threadIdx.x, wid = tid >> 5, lane = tid & 31;
    const int bh = blockIdx.y, j0 = (blockIdx.x + x0) * 128;

    float facc[8][4];
#pragma unroll
    for (int a = 0; a < 8; a++)
#pragma unroll
        for (int b = 0; b < 4; b++) facc[a][b] = 0.f;

    av_issue(sbase, 0, bh, j0, 0, tid);
    for (int c = 0; c < 8; c++) {
        const uint32_t cur = (c & 1) * 49152u;
        if (c + 1 < 8) {
            av_issue(sbase, ((c & 1) ^ 1) * 49152u, bh, j0, (c + 1) * 128, tid);
            cpa_wait1();
        } else {
            cpa_wait0();
        }
        __syncthreads();
        const uint32_t Ac = cur, Vc = cur + 32768u;
#pragma unroll
        for (int ks = 0; ks < 8; ks++) {
            uint32_t a4[4];
            uint32_t aoff = SWZ256((wid * 16 + (lane & 15)) * 256 +
                                   (ks * 2 + (lane >> 4)) * 16);
            ldmx4(a4, sbase + Ac + aoff);
#pragma unroll
            for (int np = 0; np < 4; np++) {
                uint32_t boff = SWZ256((np * 16 + (lane >> 4) * 8 + (lane & 7)) * 256 +
                                       (ks * 2 + ((lane >> 3) & 1)) * 16);
                uint32_t b4[4];
                ldmx4(b4, sbase + Vc + boff);
                mmah(facc[np * 2 + 0], a4, b4);
                mmah(facc[np * 2 + 1], a4, b4 + 2);
            }
        }
        __syncthreads();
    }
    const int b = bh / Hh, h = bh % Hh;
#pragma unroll
    for (int nt = 0; nt < 8; nt++) {
        int d = nt * 8 + (lane & 3) * 2;
#pragma unroll
        for (int half = 0; half < 2; half++) {
            int s = j0 + wid * 16 + (lane >> 2) + half * 8;
            size_t o = ((size_t)(b * 1024 + s)) * 768 + h * 64 + d;
            float v0 = g_attn[o]     + facc[nt][half * 2 + 0];
            float v1 = g_attn[o + 1] + facc[nt][half * 2 + 1];
            *(uint32_t*)(g_x16 + o) = hpack(v0, v1);
        }
    }
}

// ---------------------------------------------------------------------------
extern "C" void kernel_launch(void* const* d_in, const int* in_sizes, int n_in,
                              void* d_out, int out_size) {
    const float* q     = (const float*)d_in[0];
    const float* k     = (const float*)d_in[1];
    const float* v     = (const float*)d_in[2];
    const float* amask = (const float*)d_in[3];
    const float* pb    = (const float*)d_in[4];
    const int*   vmask = (const int*)  d_in[5];
    const float* Wq    = (const float*)d_in[6];
    const float* bq    = (const float*)d_in[7];
    const float* Wk    = (const float*)d_in[8];
    const float* bk    = (const float*)d_in[9];
    const float* Wv    = (const float*)d_in[10];
    const float* bv    = (const float*)d_in[11];
    const float* Wo    = (const float*)d_in[12];
    const float* bo    = (const float*)d_in[13];
    float* out = (float*)d_out;

    const int SM_GEMM = 65536, SM_QK = 32768, SM_FUSED = 170752, SM_AV = 98304;
    static cudaStream_t s1;
    static cudaEvent_t ev_fork, ev_join, ev_f1, ev_av1;
    static bool attr_done = false;
    if (!attr_done) {
        cudaFuncSetAttribute(gemm_mma_kernel, cudaFuncAttributeMaxDynamicSharedMemorySize, SM_GEMM);
        cudaFuncSetAttribute(qk_mma_kernel, cudaFuncAttributeMaxDynamicSharedMemorySize, SM_QK);
        cudaFuncSetAttribute(fused48_kernel, cudaFuncAttributeMaxDynamicSharedMemorySize, SM_FUSED);
        cudaFuncSetAttribute(av_mma_kernel, cudaFuncAttributeMaxDynamicSharedMemorySize, SM_AV);
        cudaStreamCreateWithFlags(&s1, cudaStreamNonBlocking);
        cudaEventCreateWithFlags(&ev_fork, cudaEventDisableTiming);
        cudaEventCreateWithFlags(&ev_join, cudaEventDisableTiming);
        cudaEventCreateWithFlags(&ev_f1, cudaEventDisableTiming);
        cudaEventCreateWithFlags(&ev_av1, cudaEventDisableTiming);
        attr_done = true;
    }

    const int n4 = 4096 * 768 / 4;
    const int pb4 = 1024 * 1024 * 64 / 4;

    // fork: pbconv (grid-stride) overlaps the projection chain
    cudaEventRecord(ev_fork, (cudaStream_t)0);
    cudaStreamWaitEvent(s1, ev_fork, 0);
    pbconv_kernel<<<512, 256, 0, s1>>>(pb, pb4);
    cudaEventRecord(ev_join, s1);

    conv16_kernel<<<dim3(n4 / 256, 3), 256>>>(q, k, v, n4);
    dim3 tthr(32, 32), tgrd(24, 24, 4);
    transpose_conv_kernel<<<tgrd, tthr>>>(Wq, Wk, Wv, Wo);
    gemm_mma_kernel<<<dim3(6, 32, 3), 256, SM_GEMM>>>(bq, bk, bv, nullptr, 0);
    qk_mma_kernel<<<dim3(8, 8, 48), 256, SM_QK>>>();

    // join: fused needs pb16
    cudaStreamWaitEvent((cudaStream_t)0, ev_join, 0);
    fused48_kernel<<<512, 256, SM_FUSED>>>(amask, vmask, 0);
    cudaEventRecord(ev_f1, (cudaStream_t)0);
    fused48_kernel<<<512, 256, SM_FUSED>>>(amask, vmask, 512);

    // av half 1 on side stream, overlapped with fused half 2
    cudaStreamWaitEvent(s1, ev_f1, 0);
    av_mma_kernel<<<dim3(4, 48), 256, SM_AV, s1>>>(0);
    cudaEventRecord(ev_av1, s1);

    // av half 2 on main stream, then out projection
    av_mma_kernel<<<dim3(4, 48), 256, SM_AV>>>(4);
    cudaStreamWaitEvent((cudaStream_t)0, ev_av1, 0);
    gemm_mma_kernel<<<dim3(6, 32, 1), 256, SM_GEMM>>>(bo, nullptr, nullptr, out, 1);
}

// round 16
// speedup vs baseline: 1.1800x; 1.0152x over previous
#include <cuda_runtime.h>
#include <cuda_fp16.h>
#include <cstdint>

// ---------------------------------------------------------------------------
// NEZHA-style MHA, all single-fp16 HMMA, cp.async double-buffered mainloops,
// fp16 scores (pre-scaled by 1/8 via q16); fused48: 48 bh rows per j-block;
// qk/fused/av j-half pipelined across two streams.
// B=4, S=1024, H=12, DK=DV=64, DM=768.
// ---------------------------------------------------------------------------

#define S 1024
#define Hh 12
#define BH 48
#define NEGV (-1e12f)

// ---------------- scratch -----------------------------------------------------
__device__ float g_attn[(size_t)4 * S * 768];

__device__ __align__(16) __half g_s16[(size_t)BH * S * S];      // scores, 100 MB
__device__ __align__(16) __half g_x16[(size_t)3 * 4096 * 768];
__device__ __align__(16) __half g_wt16[(size_t)4 * 768 * 768];
__device__ __align__(16) __half g_q16[(size_t)BH * S * 64];     // pre-scaled 1/8
__device__ __align__(16) __half g_k16[(size_t)BH * S * 64];
__device__ __align__(16) __half g_vwt16[(size_t)BH * 64 * S];   // [bh][d][s]
__device__ __align__(16) __half g_A16[(size_t)BH * S * S];      // 100 MB
__device__ __align__(16) __half g_pb16[(size_t)S * S * 64];     // [j][k][d] 128MB

// ---------------- helpers -----------------------------------------------------
__device__ __forceinline__ uint32_t smem_to_u32(const void* p) {
    uint32_t a;
    asm("{ .reg .u64 t; cvta.to.shared.u64 t, %1; cvt.u32.u64 %0, t; }"
        : "=r"(a) : "l"(p));
    return a;
}
#define SWZ(o)    ((uint32_t)(o) ^ ((((uint32_t)(o)) >> 3) & 0x70))
#define SWZ256(o) ((uint32_t)(o) ^ ((((uint32_t)(o)) >> 4) & 0x70))

__device__ __forceinline__ void ldmx4(uint32_t* r, uint32_t a) {
    asm volatile("ldmatrix.sync.aligned.m8n8.x4.shared.b16 {%0,%1,%2,%3}, [%4];"
                 : "=r"(r[0]), "=r"(r[1]), "=r"(r[2]), "=r"(r[3]) : "r"(a));
}
__device__ __forceinline__ void ldmx2t(uint32_t* r, uint32_t a) {
    asm volatile("ldmatrix.sync.aligned.m8n8.x2.trans.shared.b16 {%0,%1}, [%2];"
                 : "=r"(r[0]), "=r"(r[1]) : "r"(a));
}
__device__ __forceinline__ void mmah(float* c, const uint32_t* a,
                                     const uint32_t* b) {
    asm volatile(
        "mma.sync.aligned.m16n8k16.row.col.f32.f16.f16.f32 "
        "{%0,%1,%2,%3},{%4,%5,%6,%7},{%8,%9},{%0,%1,%2,%3};"
        : "+f"(c[0]), "+f"(c[1]), "+f"(c[2]), "+f"(c[3])
        : "r"(a[0]), "r"(a[1]), "r"(a[2]), "r"(a[3]), "r"(b[0]), "r"(b[1]));
}
__device__ __forceinline__ uint32_t hpack(float a, float b) {
    __half2 t = __floats2half2_rn(a, b);
    return *(uint32_t*)&t;
}
__device__ __forceinline__ uint2 cvt4(float4 v) {
    uint2 r;
    r.x = hpack(v.x, v.y);
    r.y = hpack(v.z, v.w);
    return r;
}
__device__ __forceinline__ void cpa16(uint32_t dst, const void* src) {
    asm volatile("cp.async.cg.shared.global [%0], [%1], 16;"
                 :: "r"(dst), "l"(src) : "memory");
}
__device__ __forceinline__ void cpa_commit() {
    asm volatile("cp.async.commit_group;" ::: "memory");
}
__device__ __forceinline__ void cpa_wait0() {
    asm volatile("cp.async.wait_group 0;" ::: "memory");
}
__device__ __forceinline__ void cpa_wait1() {
    asm volatile("cp.async.wait_group 1;" ::: "memory");
}

// ---------------- conversion kernels ------------------------------------------
__global__ void conv16_kernel(const float* __restrict__ s0,
                              const float* __restrict__ s1,
                              const float* __restrict__ s2, int n4) {
    int i = blockIdx.x * blockDim.x + threadIdx.x;
    if (i >= n4) return;
    int slot = blockIdx.y;
    const float* s = (slot == 0) ? s0 : (slot == 1 ? s1 : s2);
    float4 v = ((const float4*)s)[i];
    *(uint2*)(g_x16 + (size_t)slot * 4096 * 768 + (size_t)i * 4) = cvt4(v);
}

__global__ void transpose_conv_kernel(const float* __restrict__ W0,
                                      const float* __restrict__ W1,
                                      const float* __restrict__ W2,
                                      const float* __restrict__ W3) {
    __shared__ float t[32][33];
    int slot = blockIdx.z;
    const float* W = (slot == 0) ? W0 : (slot == 1) ? W1 : (slot == 2) ? W2 : W3;
    int tx = threadIdx.x, ty = threadIdx.y;
    int k = blockIdx.y * 32 + ty, n = blockIdx.x * 32 + tx;
    t[ty][tx] = W[(size_t)k * 768 + n];
    __syncthreads();
    int n2 = blockIdx.x * 32 + ty, k2 = blockIdx.y * 32 + tx;
    g_wt16[(size_t)slot * 768 * 768 + (size_t)n2 * 768 + k2] = __float2half(t[tx][ty]);
}

__global__ __launch_bounds__(256) void pbconv_kernel(const float* __restrict__ pb, int n4) {
    for (int i = blockIdx.x * blockDim.x + threadIdx.x; i < n4;
         i += gridDim.x * blockDim.x) {
        float4 v = ((const float4*)pb)[i];
        *(uint2*)(g_pb16 + (size_t)i * 4) = cvt4(v);
    }
}

// ---------------- HMMA dense GEMM ----------------------------------------------
__device__ __forceinline__ void gemm_issue(uint32_t sbase, uint32_t bufoff,
        const __half* xx, const __half* wt, int bm, int bn, int k0, int tid) {
#pragma unroll
    for (int i = 0; i < 8; i++) {
        int idx = tid + i * 256;
        int bsel = idx >> 10, rc = idx & 1023;
        int row = rc >> 3, q = rc & 7;
        uint32_t dst = bufoff + (bsel ? 16384u : 0u) + SWZ(row * 128 + q * 16);
        const __half* src = bsel ? (wt + (size_t)(bn + row) * 768 + k0 + q * 8)
                                 : (xx + (size_t)(bm + row) * 768 + k0 + q * 8);
        cpa16(sbase + dst, src);
    }
    cpa_commit();
}

__global__ __launch_bounds__(256) void gemm_mma_kernel(
    const float* __restrict__ b0, const float* __restrict__ b1,
    const float* __restrict__ b2, float* __restrict__ yout, int mode)
{
    extern __shared__ __align__(128) char smem[];
    const uint32_t sbase = smem_to_u32(smem);
    const int tid = threadIdx.x, wid = tid >> 5, lane = tid & 31;
    const int z = blockIdx.z;
    const int bm = blockIdx.y * 128, bn = blockIdx.x * 128;
    const int xsel = (mode == 0) ? z : 0;
    const int wsel = (mode == 0) ? z : 3;
    const __half* xx = g_x16 + (size_t)xsel * 4096 * 768;
    const __half* wt = g_wt16 + (size_t)wsel * 768 * 768;
    const float* bias = (mode == 1) ? b0 : (z == 0 ? b0 : (z == 1 ? b1 : b2));

    const int wm = (wid >> 1) * 32, wn = (wid & 1) * 64;
    float acc[2][8][4];
#pragma unroll
    for (int a = 0; a < 2; a++)
#pragma unroll
        for (int b = 0; b < 8; b++)
#pragma unroll
            for (int c = 0; c < 4; c++) acc[a][b][c] = 0.f;

    gemm_issue(sbase, 0, xx, wt, bm, bn, 0, tid);
    for (int st = 0; st < 12; st++) {
        const int cur = st & 1;
        if (st + 1 < 12) {
            gemm_issue(sbase, (cur ^ 1) * 32768u, xx, wt, bm, bn, (st + 1) * 64, tid);
            cpa_wait1();
        } else {
            cpa_wait0();
        }
        __syncthreads();
        const uint32_t Ac = cur * 32768u, Bc = Ac + 16384u;
#pragma unroll
        for (int kk = 0; kk < 4; kk++) {
            uint32_t a4[2][4];
            uint32_t aoff = SWZ((wm + (lane & 15)) * 128 + (kk * 2 + (lane >> 4)) * 16);
            ldmx4(a4[0], sbase + Ac + aoff);
            ldmx4(a4[1], sbase + Ac + aoff + 2048);
            uint32_t boff = SWZ((wn + (lane >> 4) * 8 + (lane & 7)) * 128 +
                                (kk * 2 + ((lane >> 3) & 1)) * 16);
#pragma unroll
            for (int ntp = 0; ntp < 4; ntp++) {
                uint32_t b4[4];
                ldmx4(b4, sbase + Bc + boff + ntp * 2048);
#pragma unroll
                for (int mt = 0; mt < 2; mt++) {
                    mmah(acc[mt][ntp * 2 + 0], a4[mt], b4);
                    mmah(acc[mt][ntp * 2 + 1], a4[mt], b4 + 2);
                }
            }
        }
        __syncthreads();
    }

    if (mode == 0 && z == 2) {
        __half* Th = (__half*)smem;               // [128][136]
#pragma unroll
        for (int mt = 0; mt < 2; mt++) {
#pragma unroll
            for (int nt = 0; nt < 8; nt++) {
                int cl = wn + nt * 8 + (lane & 3) * 2;
                float bx = bias[bn + cl], by = bias[bn + cl + 1];
#pragma unroll
                for (int half = 0; half < 2; half++) {
                    int rl = wm + mt * 16 + (lane >> 2) + half * 8;
                    Th[cl * 136 + rl]       = __float2half(acc[mt][nt][half * 2 + 0] + bx);
                    Th[(cl + 1) * 136 + rl] = __float2half(acc[mt][nt][half * 2 + 1] + by);
                }
            }
        }
        __syncthreads();
        int b = bm >> 10, s0 = bm & 1023;
#pragma unroll
        for (int it = 0; it < 8; it++) {
            int g = tid + it * 256;
            int cl = g >> 4, q = g & 15;
            int cg = bn + cl, h = cg >> 6, d = cg & 63;
            size_t o = (((size_t)(b * Hh + h)) * 64 + d) * 1024 + s0 + q * 8;
            *(uint4*)(g_vwt16 + o) = *(uint4*)&Th[cl * 136 + q * 8];
        }
        return;
    }

#pragma unroll
    for (int mt = 0; mt < 2; mt++) {
#pragma unroll
        for (int nt = 0; nt < 8; nt++) {
            int col = bn + wn + nt * 8 + (lane & 3) * 2;
            float bx = bias[col], by = bias[col + 1];
#pragma unroll
            for (int half = 0; half < 2; half++) {
                int row = bm + wm + mt * 16 + (lane >> 2) + half * 8;
                float v0 = acc[mt][nt][half * 2 + 0] + bx;
                float v1 = acc[mt][nt][half * 2 + 1] + by;
                if (mode == 1) {
                    yout[(size_t)row * 768 + col]     = v0;
                    yout[(size_t)row * 768 + col + 1] = v1;
                } else {
                    int b = row >> 10, s = row & 1023;
                    int h = col >> 6, d = col & 63;
                    size_t base = ((size_t)(b * Hh + h) * S + s) * 64 + d;
                    if (z == 0) {          // Q: fold the softmax 1/8 scale here
                        g_q16[base]     = __float2half(v0 * 0.125f);
                        g_q16[base + 1] = __float2half(v1 * 0.125f);
                    } else {
                        g_k16[base]     = __float2half(v0);
                        g_k16[base + 1] = __float2half(v1);
                    }
                }
            }
        }
    }
}

// ---------------- HMMA QK^T (writes fp16 scores; y0 splits j) -------------------
__global__ __launch_bounds__(256) void qk_mma_kernel(int y0) {
    extern __shared__ __align__(128) char smem[];
    const uint32_t Ao = 0, Bo = 16384;
    const uint32_t sbase = smem_to_u32(smem);
    const int tid = threadIdx.x, wid = tid >> 5, lane = tid & 31;
    const int bh = blockIdx.z;
    const int bj = (blockIdx.y + y0) * 128, bk = blockIdx.x * 128;
    const int wm = (wid >> 1) * 32, wn = (wid & 1) * 64;

    const size_t qb = ((size_t)bh * S + bj) * 64;
    const size_t kb = ((size_t)bh * S + bk) * 64;
#pragma unroll
    for (int i = 0; i < 8; i++) {
        int idx = tid + i * 256;
        int buf = idx >> 10, rc = idx & 1023;
        int row = rc >> 3, q = rc & 7;
        uint32_t dst = SWZ(row * 128 + q * 16);
        const __half* src = buf ? (g_k16 + kb + (size_t)row * 64 + q * 8)
                                : (g_q16 + qb + (size_t)row * 64 + q * 8);
        cpa16(sbase + (buf ? Bo : Ao) + dst, src);
    }
    cpa_commit();
    cpa_wait0();
    __syncthreads();

    float acc[2][8][4];
#pragma unroll
    for (int a = 0; a < 2; a++)
#pragma unroll
        for (int b = 0; b < 8; b++)
#pragma unroll
            for (int c = 0; c < 4; c++) acc[a][b][c] = 0.f;

#pragma unroll
    for (int kk = 0; kk < 4; kk++) {
        uint32_t a4[2][4];
        uint32_t aoff = SWZ((wm + (lane & 15)) * 128 + (kk * 2 + (lane >> 4)) * 16);
        ldmx4(a4[0], sbase + Ao + aoff);
        ldmx4(a4[1], sbase + Ao + aoff + 2048);
        uint32_t boff = SWZ((wn + (lane >> 4) * 8 + (lane & 7)) * 128 +
                            (kk * 2 + ((lane >> 3) & 1)) * 16);
#pragma unroll
        for (int ntp = 0; ntp < 4; ntp++) {
            uint32_t b4[4];
            ldmx4(b4, sbase + Bo + boff + ntp * 2048);
#pragma unroll
            for (int mt = 0; mt < 2; mt++) {
                mmah(acc[mt][ntp * 2 + 0], a4[mt], b4);
                mmah(acc[mt][ntp * 2 + 1], a4[mt], b4 + 2);
            }
        }
    }

#pragma unroll
    for (int mt = 0; mt < 2; mt++) {
#pragma unroll
        for (int nt = 0; nt < 8; nt++) {
            int col = bk + wn + nt * 8 + (lane & 3) * 2;
#pragma unroll
            for (int half = 0; half < 2; half++) {
                int row = bj + wm + mt * 16 + (lane >> 2) + half * 8;
                size_t idx = ((size_t)bh << 20) + ((size_t)row << 10) + col;
                *(uint32_t*)(g_s16 + idx) =
                    hpack(acc[mt][nt][half * 2 + 0], acc[mt][nt][half * 2 + 1]);
            }
        }
    }
}

// ---------------------------------------------------------------------------
// fused48: one block per j covers ALL 48 bh. S16[48][1032] fp16 smem scores.
// ---------------------------------------------------------------------------
__device__ __forceinline__ void pb_issue(uint32_t sbase, uint32_t off,
                                         int j, int k0, int tid) {
#pragma unroll
    for (int it = 0; it < 4; it++) {
        int idx = tid + it * 256;
        int kk = idx >> 3, q = idx & 7;
        cpa16(sbase + off + SWZ(kk * 128 + q * 16),
              g_pb16 + ((size_t)j * 1024 + k0 + kk) * 64 + q * 8);
    }
    cpa_commit();
}

__global__ __launch_bounds__(256) void fused48_kernel(
    const float* __restrict__ amask, const int* __restrict__ vmask, int joff)
{
    extern __shared__ __align__(128) char smem[];
    __half* S16 = (__half*)smem;                  // [48][1032] = 99072
    const uint32_t PB0 = 99072, PB1 = 115456;     // 2 x 16KB pb buffers
    const uint32_t QHo = 131840;                  // [48][128B] swizzled, 6144
    float* AM = (float*)(smem + 137984);          // [1024] 4KB
    float* Mf = (float*)(smem + 142080);          // [4][1024] 16KB
    const uint32_t AHc = 158464;                  // [48][256B] SWZ256, 12288
    const uint32_t sbase = smem_to_u32(smem);
    const int tid = threadIdx.x, wid = tid >> 5, lane = tid & 31;
    const int j = blockIdx.x + joff;

    pb_issue(sbase, PB0, j, 0, tid);

#pragma unroll
    for (int it = 0; it < 24; it++) {
        int idx = tid + it * 256;
        int row = idx >> 7, g = idx & 127;
        *(uint4*)&S16[row * 1032 + g * 8] =
            *(const uint4*)(g_s16 + (((size_t)row) << 20) +
                            ((size_t)j << 10) + g * 8);
    }
#pragma unroll
    for (int it = 0; it < 2; it++) {
        int idx = tid + it * 256;
        if (idx < 384) {
            int r = idx >> 3, q = idx & 7;
            uint32_t dst = SWZ(r * 128 + q * 16);
            *(uint4*)(smem + QHo + dst) =
                *(const uint4*)(g_q16 + ((size_t)r * 1024 + j) * 64 + q * 8);
        }
    }
    *(float4*)&AM[tid * 4] = *(const float4*)(amask + (size_t)j * 1024 + tid * 4);
#pragma unroll
    for (int r2 = 0; r2 < 4; r2++) {
        int4 m = *(const int4*)(vmask + (size_t)r2 * 1024 + tid * 4);
        Mf[r2 * 1024 + tid * 4 + 0] = m.x ? 1.f : 0.f;
        Mf[r2 * 1024 + tid * 4 + 1] = m.y ? 1.f : 0.f;
        Mf[r2 * 1024 + tid * 4 + 2] = m.z ? 1.f : 0.f;
        Mf[r2 * 1024 + tid * 4 + 3] = m.w ? 1.f : 0.f;
    }
    __syncthreads();

    // ---- phase B: S16 += qw·pb (q pre-scaled by 1/8) ----
    for (int c = 0; c < 8; c++) {
        const uint32_t cur = (c & 1) ? PB1 : PB0;
        if (c + 1 < 8) {
            pb_issue(sbase, (c & 1) ? PB0 : PB1, j, (c + 1) * 128, tid);
            cpa_wait1();
        } else {
            cpa_wait0();
        }
        __syncthreads();
        const int k0 = c * 128;
        float frag[3][2][4];
#pragma unroll
        for (int mt = 0; mt < 3; mt++)
#pragma unroll
            for (int nt = 0; nt < 2; nt++)
#pragma unroll
                for (int e = 0; e < 4; e++) frag[mt][nt][e] = 0.f;
#pragma unroll
        for (int ks = 0; ks < 4; ks++) {
            uint32_t boff = SWZ((wid * 16 + (lane >> 4) * 8 + (lane & 7)) * 128 +
                                (ks * 2 + ((lane >> 3) & 1)) * 16);
            uint32_t b4[4];
            ldmx4(b4, sbase + cur + boff);
#pragma unroll
            for (int mt = 0; mt < 3; mt++) {
                uint32_t a4[4];
                uint32_t aoff = SWZ((mt * 16 + (lane & 15)) * 128 +
                                    (ks * 2 + (lane >> 4)) * 16);
                ldmx4(a4, sbase + QHo + aoff);
                mmah(frag[mt][0], a4, b4);
                mmah(frag[mt][1], a4, b4 + 2);
            }
        }
        const int r0 = lane >> 2, c0 = (lane & 3) * 2;
#pragma unroll
        for (int mt = 0; mt < 3; mt++)
#pragma unroll
            for (int nt = 0; nt < 2; nt++)
#pragma unroll
                for (int eh = 0; eh < 2; eh++) {
                    int row = mt * 16 + r0 + eh * 8;
                    int col = k0 + wid * 16 + nt * 8 + c0;
                    __half2* p = (__half2*)&S16[row * 1032 + col];
                    float2 old = __half22float2(*p);
                    *p = __floats2half2_rn(old.x + frag[mt][nt][eh * 2 + 0],
                                           old.y + frag[mt][nt][eh * 2 + 1]);
                }
        __syncthreads();
    }

    // ---- softmax (scale already folded into q16) ----
#pragma unroll
    for (int rr = 0; rr < 6; rr++) {
        int row = wid * 6 + rr;
        int bsel = row / Hh;
        float x[32];
        float mx = -3.4e38f;
#pragma unroll
        for (int i = 0; i < 32; i++) {
            int k = lane + i * 32;
            float m = Mf[bsel * 1024 + k];
            float val = __half2float(S16[row * 1032 + k]) + AM[k];
            x[i] = (m != 0.f) ? val : NEGV;
            mx = fmaxf(mx, x[i]);
        }
#pragma unroll
        for (int o = 16; o > 0; o >>= 1) mx = fmaxf(mx, __shfl_xor_sync(~0u, mx, o));
        float sum = 0.f;
#pragma unroll
        for (int i = 0; i < 32; i++) { x[i] = __expf(x[i] - mx); sum += x[i]; }
#pragma unroll
        for (int o = 16; o > 0; o >>= 1) sum += __shfl_xor_sync(~0u, sum, o);
        float inv = 1.f / sum;
#pragma unroll
        for (int i = 0; i < 32; i++)
            S16[row * 1032 + lane + i * 32] = __float2half(x[i] * inv);
    }
    __syncthreads();

    pb_issue(sbase, PB0, j, 0, tid);

    // ---- write A fp16 ----
#pragma unroll
    for (int it = 0; it < 24; it++) {
        int idx = tid + it * 256;
        int row = idx >> 7, g = idx & 127;
        *(uint4*)(g_A16 + (((size_t)row) << 20) + ((size_t)j << 10) + g * 8) =
            *(uint4*)&S16[row * 1032 + g * 8];
    }

    // ---- phase C: attn[0..47][d] = A·pb ----
    float facc[3][4];
#pragma unroll
    for (int mt = 0; mt < 3; mt++)
#pragma unroll
        for (int e = 0; e < 4; e++) facc[mt][e] = 0.f;
    const int w16 = wid * 16;
    for (int c = 0; c < 8; c++) {
        const uint32_t cur = (c & 1) ? PB1 : PB0;
        const int k0 = c * 128;
#pragma unroll
        for (int it = 0; it < 3; it++) {
            int idx = tid + it * 256;
            int row = idx >> 4, q = idx & 15;
            uint32_t dst = SWZ256(row * 256 + q * 16);
            *(uint4*)(smem + AHc + dst) = *(uint4*)&S16[row * 1032 + k0 + q * 8];
        }
        if (c + 1 < 8) {
            pb_issue(sbase, (c & 1) ? PB0 : PB1, j, (c + 1) * 128, tid);
            cpa_wait1();
        } else {
            cpa_wait0();
        }
        __syncthreads();
#pragma unroll
        for (int ks = 0; ks < 8; ks++) {
            uint32_t bt[2];
            uint32_t boff = SWZ((ks * 16 + (lane & 15)) * 128 + w16);
            ldmx2t(bt, sbase + cur + boff);
#pragma unroll
            for (int mt = 0; mt < 3; mt++) {
                uint32_t a4[4];
                uint32_t aoff = SWZ256((mt * 16 + (lane & 15)) * 256 +
                                       (ks * 2 + (lane >> 4)) * 16);
                ldmx4(a4, sbase + AHc + aoff);
                mmah(facc[mt], a4, bt);
            }
        }
        __syncthreads();
    }
    {
        int d = wid * 8 + (lane & 3) * 2;
#pragma unroll
        for (int mt = 0; mt < 3; mt++)
#pragma unroll
            for (int half = 0; half < 2; half++) {
                int bh = mt * 16 + (lane >> 2) + half * 8;
                int b = bh / Hh, h = bh % Hh;
                size_t o = ((size_t)(b * 1024 + j)) * 768 + h * 64 + d;
                g_attn[o]     = facc[mt][half * 2 + 0];
                g_attn[o + 1] = facc[mt][half * 2 + 1];
            }
    }
}

// ---------------------------------------------------------------------------
// av: x16[0] = fp16(attn_pb + A·vw). Grid (4, 48), jtile = blockIdx.x + x0.
// ---------------------------------------------------------------------------
__device__ __forceinline__ void av_issue(uint32_t sbase, uint32_t bufoff,
                                         int bh, int j0, int k0, int tid) {
#pragma unroll
    for (int it = 0; it < 12; it++) {
        int idx = tid + it * 256;
        if (idx < 2048) {
            int row = idx >> 4, q = idx & 15;
            cpa16(sbase + bufoff + SWZ256(row * 256 + q * 16),
                  g_A16 + (((size_t)bh) << 20) +
                  ((size_t)(j0 + row) << 10) + k0 + q * 8);
        } else {
            int rc = idx - 2048;
            int d = rc >> 4, q = rc & 15;
            cpa16(sbase + bufoff + 32768u + SWZ256(d * 256 + q * 16),
                  g_vwt16 + ((size_t)bh * 64 + d) * 1024 + k0 + q * 8);
        }
    }
    cpa_commit();
}

__global__ __launch_bounds__(256) void av_mma_kernel(int x0) {
    extern __shared__ __align__(128) char smem[];
    const uint32_t sbase = smem_to_u32(smem);
    const int tid = threadIdx.x, wid = tid >> 5, lane = tid & 31;
    const int bh = blockIdx.y, j0 = (blockIdx.x + x0) * 128;

    float facc[8][4];
#pragma unroll
    for (int a = 0; a < 8; a++)
#pragma unroll
        for (int b = 0; b < 4; b++) facc[a][b] = 0.f;

    av_issue(sbase, 0, bh, j0, 0, tid);
    for (int c = 0; c < 8; c++) {
        const uint32_t cur = (c & 1) * 49152u;
        if (c + 1 < 8) {
            av_issue(sbase, ((c & 1) ^ 1) * 49152u, bh, j0, (c + 1) * 128, tid);
            cpa_wait1();
        } else {
            cpa_wait0();
        }
        __syncthreads();
        const uint32_t Ac = cur, Vc = cur + 32768u;
#pragma unroll
        for (int ks = 0; ks < 8; ks++) {
            uint32_t a4[4];
            uint32_t aoff = SWZ256((wid * 16 + (lane & 15)) * 256 +
                                   (ks * 2 + (lane >> 4)) * 16);
            ldmx4(a4, sbase + Ac + aoff);
#pragma unroll
            for (int np = 0; np < 4; np++) {
                uint32_t boff = SWZ256((np * 16 + (lane >> 4) * 8 + (lane & 7)) * 256 +
                                       (ks * 2 + ((lane >> 3) & 1)) * 16);
                uint32_t b4[4];
                ldmx4(b4, sbase + Vc + boff);
                mmah(facc[np * 2 + 0], a4, b4);
                mmah(facc[np * 2 + 1], a4, b4 + 2);
            }
        }
        __syncthreads();
    }
    const int b = bh / Hh, h = bh % Hh;
#pragma unroll
    for (int nt = 0; nt < 8; nt++) {
        int d = nt * 8 + (lane & 3) * 2;
#pragma unroll
        for (int half = 0; half < 2; half++) {
            int s = j0 + wid * 16 + (lane >> 2) + half * 8;
            size_t o = ((size_t)(b * 1024 + s)) * 768 + h * 64 + d;
            float v0 = g_attn[o]     + facc[nt][half * 2 + 0];
            float v1 = g_attn[o + 1] + facc[nt][half * 2 + 1];
            *(uint32_t*)(g_x16 + o) = hpack(v0, v1);
        }
    }
}

// ---------------------------------------------------------------------------
extern "C" void kernel_launch(void* const* d_in, const int* in_sizes, int n_in,
                              void* d_out, int out_size) {
    const float* q     = (const float*)d_in[0];
    const float* k     = (const float*)d_in[1];
    const float* v     = (const float*)d_in[2];
    const float* amask = (const float*)d_in[3];
    const float* pb    = (const float*)d_in[4];
    const int*   vmask = (const int*)  d_in[5];
    const float* Wq    = (const float*)d_in[6];
    const float* bq    = (const float*)d_in[7];
    const float* Wk    = (const float*)d_in[8];
    const float* bk    = (const float*)d_in[9];
    const float* Wv    = (const float*)d_in[10];
    const float* bv    = (const float*)d_in[11];
    const float* Wo    = (const float*)d_in[12];
    const float* bo    = (const float*)d_in[13];
    float* out = (float*)d_out;

    const int SM_GEMM = 65536, SM_QK = 32768, SM_FUSED = 170752, SM_AV = 98304;
    static cudaStream_t s1;
    static cudaEvent_t ev_fork, ev_join, ev_gemm, ev_qk2, ev_f1, ev_av1;
    static bool attr_done = false;
    if (!attr_done) {
        cudaFuncSetAttribute(gemm_mma_kernel, cudaFuncAttributeMaxDynamicSharedMemorySize, SM_GEMM);
        cudaFuncSetAttribute(qk_mma_kernel, cudaFuncAttributeMaxDynamicSharedMemorySize, SM_QK);
        cudaFuncSetAttribute(fused48_kernel, cudaFuncAttributeMaxDynamicSharedMemorySize, SM_FUSED);
        cudaFuncSetAttribute(av_mma_kernel, cudaFuncAttributeMaxDynamicSharedMemorySize, SM_AV);
        cudaStreamCreateWithFlags(&s1, cudaStreamNonBlocking);
        cudaEventCreateWithFlags(&ev_fork, cudaEventDisableTiming);
        cudaEventCreateWithFlags(&ev_join, cudaEventDisableTiming);
        cudaEventCreateWithFlags(&ev_gemm, cudaEventDisableTiming);
        cudaEventCreateWithFlags(&ev_qk2, cudaEventDisableTiming);
        cudaEventCreateWithFlags(&ev_f1, cudaEventDisableTiming);
        cudaEventCreateWithFlags(&ev_av1, cudaEventDisableTiming);
        attr_done = true;
    }

    const int n4 = 4096 * 768 / 4;
    const int pb4 = 1024 * 1024 * 64 / 4;

    // fork: pbconv on side stream
    cudaEventRecord(ev_fork, (cudaStream_t)0);
    cudaStreamWaitEvent(s1, ev_fork, 0);
    pbconv_kernel<<<512, 256, 0, s1>>>(pb, pb4);
    cudaEventRecord(ev_join, s1);

    conv16_kernel<<<dim3(n4 / 256, 3), 256>>>(q, k, v, n4);
    dim3 tthr(32, 32), tgrd(24, 24, 4);
    transpose_conv_kernel<<<tgrd, tthr>>>(Wq, Wk, Wv, Wo);
    gemm_mma_kernel<<<dim3(6, 32, 3), 256, SM_GEMM>>>(bq, bk, bv, nullptr, 0);
    cudaEventRecord(ev_gemm, (cudaStream_t)0);

    // qk half 2 on side stream (after pbconv + gemm), concurrent with
    // qk half 1 + fused half 1 on main
    cudaStreamWaitEvent(s1, ev_gemm, 0);
    qk_mma_kernel<<<dim3(8, 4, 48), 256, SM_QK, s1>>>(4);
    cudaEventRecord(ev_qk2, s1);

    qk_mma_kernel<<<dim3(8, 4, 48), 256, SM_QK>>>(0);
    cudaStreamWaitEvent((cudaStream_t)0, ev_join, 0);
    fused48_kernel<<<512, 256, SM_FUSED>>>(amask, vmask, 0);
    cudaEventRecord(ev_f1, (cudaStream_t)0);
    cudaStreamWaitEvent((cudaStream_t)0, ev_qk2, 0);
    fused48_kernel<<<512, 256, SM_FUSED>>>(amask, vmask, 512);

    // av half 1 on side stream, overlapped with fused half 2
    cudaStreamWaitEvent(s1, ev_f1, 0);
    av_mma_kernel<<<dim3(4, 48), 256, SM_AV, s1>>>(0);
    cudaEventRecord(ev_av1, s1);

    // av half 2 on main stream, then out projection
    av_mma_kernel<<<dim3(4, 48), 256, SM_AV>>>(4);
    cudaStreamWaitEvent((cudaStream_t)0, ev_av1, 0);
    gemm_mma_kernel<<<dim3(6, 32, 1), 256, SM_GEMM>>>(bo, nullptr, nullptr, out, 1);
}

// round 17
// speedup vs baseline: 1.2218x; 1.0354x over previous
#include <cuda_runtime.h>
#include <cuda_fp16.h>
#include <cstdint>

// ---------------------------------------------------------------------------
// NEZHA-style MHA, all single-fp16 HMMA, cp.async double-buffered mainloops,
// fp16 scores (pre-scaled by 1/8 via q16); fused48: 48 bh rows per j-block
// with direct-from-S16 ldmatrix in phase C; 2 blocks/SM gemm.
// B=4, S=1024, H=12, DK=DV=64, DM=768.
// ---------------------------------------------------------------------------

#define S 1024
#define Hh 12
#define BH 48
#define NEGV (-1e12f)

// ---------------- scratch -----------------------------------------------------
__device__ float g_attn[(size_t)4 * S * 768];

__device__ __align__(16) __half g_s16[(size_t)BH * S * S];      // scores, 100 MB
__device__ __align__(16) __half g_x16[(size_t)3 * 4096 * 768];
__device__ __align__(16) __half g_wt16[(size_t)4 * 768 * 768];
__device__ __align__(16) __half g_q16[(size_t)BH * S * 64];     // pre-scaled 1/8
__device__ __align__(16) __half g_k16[(size_t)BH * S * 64];
__device__ __align__(16) __half g_vwt16[(size_t)BH * 64 * S];   // [bh][d][s]
__device__ __align__(16) __half g_A16[(size_t)BH * S * S];      // 100 MB
__device__ __align__(16) __half g_pb16[(size_t)S * S * 64];     // [j][k][d] 128MB

// ---------------- helpers -----------------------------------------------------
__device__ __forceinline__ uint32_t smem_to_u32(const void* p) {
    uint32_t a;
    asm("{ .reg .u64 t; cvta.to.shared.u64 t, %1; cvt.u32.u64 %0, t; }"
        : "=r"(a) : "l"(p));
    return a;
}
#define SWZ(o)    ((uint32_t)(o) ^ ((((uint32_t)(o)) >> 3) & 0x70))
#define SWZ256(o) ((uint32_t)(o) ^ ((((uint32_t)(o)) >> 4) & 0x70))

__device__ __forceinline__ void ldmx4(uint32_t* r, uint32_t a) {
    asm volatile("ldmatrix.sync.aligned.m8n8.x4.shared.b16 {%0,%1,%2,%3}, [%4];"
                 : "=r"(r[0]), "=r"(r[1]), "=r"(r[2]), "=r"(r[3]) : "r"(a));
}
__device__ __forceinline__ void ldmx2t(uint32_t* r, uint32_t a) {
    asm volatile("ldmatrix.sync.aligned.m8n8.x2.trans.shared.b16 {%0,%1}, [%2];"
                 : "=r"(r[0]), "=r"(r[1]) : "r"(a));
}
__device__ __forceinline__ void mmah(float* c, const uint32_t* a,
                                     const uint32_t* b) {
    asm volatile(
        "mma.sync.aligned.m16n8k16.row.col.f32.f16.f16.f32 "
        "{%0,%1,%2,%3},{%4,%5,%6,%7},{%8,%9},{%0,%1,%2,%3};"
        : "+f"(c[0]), "+f"(c[1]), "+f"(c[2]), "+f"(c[3])
        : "r"(a[0]), "r"(a[1]), "r"(a[2]), "r"(a[3]), "r"(b[0]), "r"(b[1]));
}
__device__ __forceinline__ uint32_t hpack(float a, float b) {
    __half2 t = __floats2half2_rn(a, b);
    return *(uint32_t*)&t;
}
__device__ __forceinline__ uint2 cvt4(float4 v) {
    uint2 r;
    r.x = hpack(v.x, v.y);
    r.y = hpack(v.z, v.w);
    return r;
}
__device__ __forceinline__ void cpa16(uint32_t dst, const void* src) {
    asm volatile("cp.async.cg.shared.global [%0], [%1], 16;"
                 :: "r"(dst), "l"(src) : "memory");
}
__device__ __forceinline__ void cpa_commit() {
    asm volatile("cp.async.commit_group;" ::: "memory");
}
__device__ __forceinline__ void cpa_wait0() {
    asm volatile("cp.async.wait_group 0;" ::: "memory");
}
__device__ __forceinline__ void cpa_wait1() {
    asm volatile("cp.async.wait_group 1;" ::: "memory");
}

// ---------------- conversion kernels ------------------------------------------
__global__ void conv16_kernel(const float* __restrict__ s0,
                              const float* __restrict__ s1,
                              const float* __restrict__ s2, int n4) {
    int i = blockIdx.x * blockDim.x + threadIdx.x;
    if (i >= n4) return;
    int slot = blockIdx.y;
    const float* s = (slot == 0) ? s0 : (slot == 1 ? s1 : s2);
    float4 v = ((const float4*)s)[i];
    *(uint2*)(g_x16 + (size_t)slot * 4096 * 768 + (size_t)i * 4) = cvt4(v);
}

__global__ void transpose_conv_kernel(const float* __restrict__ W0,
                                      const float* __restrict__ W1,
                                      const float* __restrict__ W2,
                                      const float* __restrict__ W3) {
    __shared__ float t[32][33];
    int slot = blockIdx.z;
    const float* W = (slot == 0) ? W0 : (slot == 1) ? W1 : (slot == 2) ? W2 : W3;
    int tx = threadIdx.x, ty = threadIdx.y;
    int k = blockIdx.y * 32 + ty, n = blockIdx.x * 32 + tx;
    t[ty][tx] = W[(size_t)k * 768 + n];
    __syncthreads();
    int n2 = blockIdx.x * 32 + ty, k2 = blockIdx.y * 32 + tx;
    g_wt16[(size_t)slot * 768 * 768 + (size_t)n2 * 768 + k2] = __float2half(t[tx][ty]);
}

__global__ __launch_bounds__(256) void pbconv_kernel(const float* __restrict__ pb, int n4) {
    for (int i = blockIdx.x * blockDim.x + threadIdx.x; i < n4;
         i += gridDim.x * blockDim.x) {
        float4 v = ((const float4*)pb)[i];
        *(uint2*)(g_pb16 + (size_t)i * 4) = cvt4(v);
    }
}

// ---------------- HMMA dense GEMM (2 blocks/SM) ---------------------------------
__device__ __forceinline__ void gemm_issue(uint32_t sbase, uint32_t bufoff,
        const __half* xx, const __half* wt, int bm, int bn, int k0, int tid) {
#pragma unroll
    for (int i = 0; i < 8; i++) {
        int idx = tid + i * 256;
        int bsel = idx >> 10, rc = idx & 1023;
        int row = rc >> 3, q = rc & 7;
        uint32_t dst = bufoff + (bsel ? 16384u : 0u) + SWZ(row * 128 + q * 16);
        const __half* src = bsel ? (wt + (size_t)(bn + row) * 768 + k0 + q * 8)
                                 : (xx + (size_t)(bm + row) * 768 + k0 + q * 8);
        cpa16(sbase + dst, src);
    }
    cpa_commit();
}

__global__ __launch_bounds__(256, 2) void gemm_mma_kernel(
    const float* __restrict__ b0, const float* __restrict__ b1,
    const float* __restrict__ b2, float* __restrict__ yout, int mode)
{
    extern __shared__ __align__(128) char smem[];
    const uint32_t sbase = smem_to_u32(smem);
    const int tid = threadIdx.x, wid = tid >> 5, lane = tid & 31;
    const int z = blockIdx.z;
    const int bm = blockIdx.y * 128, bn = blockIdx.x * 128;
    const int xsel = (mode == 0) ? z : 0;
    const int wsel = (mode == 0) ? z : 3;
    const __half* xx = g_x16 + (size_t)xsel * 4096 * 768;
    const __half* wt = g_wt16 + (size_t)wsel * 768 * 768;
    const float* bias = (mode == 1) ? b0 : (z == 0 ? b0 : (z == 1 ? b1 : b2));

    const int wm = (wid >> 1) * 32, wn = (wid & 1) * 64;
    float acc[2][8][4];
#pragma unroll
    for (int a = 0; a < 2; a++)
#pragma unroll
        for (int b = 0; b < 8; b++)
#pragma unroll
            for (int c = 0; c < 4; c++) acc[a][b][c] = 0.f;

    gemm_issue(sbase, 0, xx, wt, bm, bn, 0, tid);
    for (int st = 0; st < 12; st++) {
        const int cur = st & 1;
        if (st + 1 < 12) {
            gemm_issue(sbase, (cur ^ 1) * 32768u, xx, wt, bm, bn, (st + 1) * 64, tid);
            cpa_wait1();
        } else {
            cpa_wait0();
        }
        __syncthreads();
        const uint32_t Ac = cur * 32768u, Bc = Ac + 16384u;
#pragma unroll
        for (int kk = 0; kk < 4; kk++) {
            uint32_t a4[2][4];
            uint32_t aoff = SWZ((wm + (lane & 15)) * 128 + (kk * 2 + (lane >> 4)) * 16);
            ldmx4(a4[0], sbase + Ac + aoff);
            ldmx4(a4[1], sbase + Ac + aoff + 2048);
            uint32_t boff = SWZ((wn + (lane >> 4) * 8 + (lane & 7)) * 128 +
                                (kk * 2 + ((lane >> 3) & 1)) * 16);
#pragma unroll
            for (int ntp = 0; ntp < 4; ntp++) {
                uint32_t b4[4];
                ldmx4(b4, sbase + Bc + boff + ntp * 2048);
#pragma unroll
                for (int mt = 0; mt < 2; mt++) {
                    mmah(acc[mt][ntp * 2 + 0], a4[mt], b4);
                    mmah(acc[mt][ntp * 2 + 1], a4[mt], b4 + 2);
                }
            }
        }
        __syncthreads();
    }

    if (mode == 0 && z == 2) {
        __half* Th = (__half*)smem;               // [128][136]
#pragma unroll
        for (int mt = 0; mt < 2; mt++) {
#pragma unroll
            for (int nt = 0; nt < 8; nt++) {
                int cl = wn + nt * 8 + (lane & 3) * 2;
                float bx = bias[bn + cl], by = bias[bn + cl + 1];
#pragma unroll
                for (int half = 0; half < 2; half++) {
                    int rl = wm + mt * 16 + (lane >> 2) + half * 8;
                    Th[cl * 136 + rl]       = __float2half(acc[mt][nt][half * 2 + 0] + bx);
                    Th[(cl + 1) * 136 + rl] = __float2half(acc[mt][nt][half * 2 + 1] + by);
                }
            }
        }
        __syncthreads();
        int b = bm >> 10, s0 = bm & 1023;
#pragma unroll
        for (int it = 0; it < 8; it++) {
            int g = tid + it * 256;
            int cl = g >> 4, q = g & 15;
            int cg = bn + cl, h = cg >> 6, d = cg & 63;
            size_t o = (((size_t)(b * Hh + h)) * 64 + d) * 1024 + s0 + q * 8;
            *(uint4*)(g_vwt16 + o) = *(uint4*)&Th[cl * 136 + q * 8];
        }
        return;
    }

#pragma unroll
    for (int mt = 0; mt < 2; mt++) {
#pragma unroll
        for (int nt = 0; nt < 8; nt++) {
            int col = bn + wn + nt * 8 + (lane & 3) * 2;
            float bx = bias[col], by = bias[col + 1];
#pragma unroll
            for (int half = 0; half < 2; half++) {
                int row = bm + wm + mt * 16 + (lane >> 2) + half * 8;
                float v0 = acc[mt][nt][half * 2 + 0] + bx;
                float v1 = acc[mt][nt][half * 2 + 1] + by;
                if (mode == 1) {
                    yout[(size_t)row * 768 + col]     = v0;
                    yout[(size_t)row * 768 + col + 1] = v1;
                } else {
                    int b = row >> 10, s = row & 1023;
                    int h = col >> 6, d = col & 63;
                    size_t base = ((size_t)(b * Hh + h) * S + s) * 64 + d;
                    if (z == 0) {
                        g_q16[base]     = __float2half(v0 * 0.125f);
                        g_q16[base + 1] = __float2half(v1 * 0.125f);
                    } else {
                        g_k16[base]     = __float2half(v0);
                        g_k16[base + 1] = __float2half(v1);
                    }
                }
            }
        }
    }
}

// ---------------- HMMA QK^T (writes fp16 scores; y0 splits j) -------------------
__global__ __launch_bounds__(256) void qk_mma_kernel(int y0) {
    extern __shared__ __align__(128) char smem[];
    const uint32_t Ao = 0, Bo = 16384;
    const uint32_t sbase = smem_to_u32(smem);
    const int tid = threadIdx.x, wid = tid >> 5, lane = tid & 31;
    const int bh = blockIdx.z;
    const int bj = (blockIdx.y + y0) * 128, bk = blockIdx.x * 128;
    const int wm = (wid >> 1) * 32, wn = (wid & 1) * 64;

    const size_t qb = ((size_t)bh * S + bj) * 64;
    const size_t kb = ((size_t)bh * S + bk) * 64;
#pragma unroll
    for (int i = 0; i < 8; i++) {
        int idx = tid + i * 256;
        int buf = idx >> 10, rc = idx & 1023;
        int row = rc >> 3, q = rc & 7;
        uint32_t dst = SWZ(row * 128 + q * 16);
        const __half* src = buf ? (g_k16 + kb + (size_t)row * 64 + q * 8)
                                : (g_q16 + qb + (size_t)row * 64 + q * 8);
        cpa16(sbase + (buf ? Bo : Ao) + dst, src);
    }
    cpa_commit();
    cpa_wait0();
    __syncthreads();

    float acc[2][8][4];
#pragma unroll
    for (int a = 0; a < 2; a++)
#pragma unroll
        for (int b = 0; b < 8; b++)
#pragma unroll
            for (int c = 0; c < 4; c++) acc[a][b][c] = 0.f;

#pragma unroll
    for (int kk = 0; kk < 4; kk++) {
        uint32_t a4[2][4];
        uint32_t aoff = SWZ((wm + (lane & 15)) * 128 + (kk * 2 + (lane >> 4)) * 16);
        ldmx4(a4[0], sbase + Ao + aoff);
        ldmx4(a4[1], sbase + Ao + aoff + 2048);
        uint32_t boff = SWZ((wn + (lane >> 4) * 8 + (lane & 7)) * 128 +
                            (kk * 2 + ((lane >> 3) & 1)) * 16);
#pragma unroll
        for (int ntp = 0; ntp < 4; ntp++) {
            uint32_t b4[4];
            ldmx4(b4, sbase + Bo + boff + ntp * 2048);
#pragma unroll
            for (int mt = 0; mt < 2; mt++) {
                mmah(acc[mt][ntp * 2 + 0], a4[mt], b4);
                mmah(acc[mt][ntp * 2 + 1], a4[mt], b4 + 2);
            }
        }
    }

#pragma unroll
    for (int mt = 0; mt < 2; mt++) {
#pragma unroll
        for (int nt = 0; nt < 8; nt++) {
            int col = bk + wn + nt * 8 + (lane & 3) * 2;
#pragma unroll
            for (int half = 0; half < 2; half++) {
                int row = bj + wm + mt * 16 + (lane >> 2) + half * 8;
                size_t idx = ((size_t)bh << 20) + ((size_t)row << 10) + col;
                *(uint32_t*)(g_s16 + idx) =
                    hpack(acc[mt][nt][half * 2 + 0], acc[mt][nt][half * 2 + 1]);
            }
        }
    }
}

// ---------------------------------------------------------------------------
// fused48: one block per j covers ALL 48 bh. S16[48][1032] fp16 smem scores.
// Phase C loads A fragments directly from S16 (row stride 2064B, conflict-free).
// ---------------------------------------------------------------------------
__device__ __forceinline__ void pb_issue(uint32_t sbase, uint32_t off,
                                         int j, int k0, int tid) {
#pragma unroll
    for (int it = 0; it < 4; it++) {
        int idx = tid + it * 256;
        int kk = idx >> 3, q = idx & 7;
        cpa16(sbase + off + SWZ(kk * 128 + q * 16),
              g_pb16 + ((size_t)j * 1024 + k0 + kk) * 64 + q * 8);
    }
    cpa_commit();
}

__global__ __launch_bounds__(256) void fused48_kernel(
    const float* __restrict__ amask, const int* __restrict__ vmask, int joff)
{
    extern __shared__ __align__(128) char smem[];
    __half* S16 = (__half*)smem;                  // [48][1032] = 99072
    const uint32_t PB0 = 99072, PB1 = 115456;     // 2 x 16KB pb buffers
    const uint32_t QHo = 131840;                  // [48][128B] swizzled, 6144
    float* AM = (float*)(smem + 137984);          // [1024] 4KB
    float* Mf = (float*)(smem + 142080);          // [4][1024] 16KB -> 158464
    const uint32_t sbase = smem_to_u32(smem);
    const int tid = threadIdx.x, wid = tid >> 5, lane = tid & 31;
    const int j = blockIdx.x + joff;

    pb_issue(sbase, PB0, j, 0, tid);

#pragma unroll
    for (int it = 0; it < 24; it++) {
        int idx = tid + it * 256;
        int row = idx >> 7, g = idx & 127;
        *(uint4*)&S16[row * 1032 + g * 8] =
            *(const uint4*)(g_s16 + (((size_t)row) << 20) +
                            ((size_t)j << 10) + g * 8);
    }
#pragma unroll
    for (int it = 0; it < 2; it++) {
        int idx = tid + it * 256;
        if (idx < 384) {
            int r = idx >> 3, q = idx & 7;
            uint32_t dst = SWZ(r * 128 + q * 16);
            *(uint4*)(smem + QHo + dst) =
                *(const uint4*)(g_q16 + ((size_t)r * 1024 + j) * 64 + q * 8);
        }
    }
    *(float4*)&AM[tid * 4] = *(const float4*)(amask + (size_t)j * 1024 + tid * 4);
#pragma unroll
    for (int r2 = 0; r2 < 4; r2++) {
        int4 m = *(const int4*)(vmask + (size_t)r2 * 1024 + tid * 4);
        Mf[r2 * 1024 + tid * 4 + 0] = m.x ? 1.f : 0.f;
        Mf[r2 * 1024 + tid * 4 + 1] = m.y ? 1.f : 0.f;
        Mf[r2 * 1024 + tid * 4 + 2] = m.z ? 1.f : 0.f;
        Mf[r2 * 1024 + tid * 4 + 3] = m.w ? 1.f : 0.f;
    }
    __syncthreads();

    // ---- phase B: S16 += qw·pb (q pre-scaled by 1/8) ----
    for (int c = 0; c < 8; c++) {
        const uint32_t cur = (c & 1) ? PB1 : PB0;
        if (c + 1 < 8) {
            pb_issue(sbase, (c & 1) ? PB0 : PB1, j, (c + 1) * 128, tid);
            cpa_wait1();
        } else {
            cpa_wait0();
        }
        __syncthreads();
        const int k0 = c * 128;
        float frag[3][2][4];
#pragma unroll
        for (int mt = 0; mt < 3; mt++)
#pragma unroll
            for (int nt = 0; nt < 2; nt++)
#pragma unroll
                for (int e = 0; e < 4; e++) frag[mt][nt][e] = 0.f;
#pragma unroll
        for (int ks = 0; ks < 4; ks++) {
            uint32_t boff = SWZ((wid * 16 + (lane >> 4) * 8 + (lane & 7)) * 128 +
                                (ks * 2 + ((lane >> 3) & 1)) * 16);
            uint32_t b4[4];
            ldmx4(b4, sbase + cur + boff);
#pragma unroll
            for (int mt = 0; mt < 3; mt++) {
                uint32_t a4[4];
                uint32_t aoff = SWZ((mt * 16 + (lane & 15)) * 128 +
                                    (ks * 2 + (lane >> 4)) * 16);
                ldmx4(a4, sbase + QHo + aoff);
                mmah(frag[mt][0], a4, b4);
                mmah(frag[mt][1], a4, b4 + 2);
            }
        }
        const int r0 = lane >> 2, c0 = (lane & 3) * 2;
#pragma unroll
        for (int mt = 0; mt < 3; mt++)
#pragma unroll
            for (int nt = 0; nt < 2; nt++)
#pragma unroll
                for (int eh = 0; eh < 2; eh++) {
                    int row = mt * 16 + r0 + eh * 8;
                    int col = k0 + wid * 16 + nt * 8 + c0;
                    __half2* p = (__half2*)&S16[row * 1032 + col];
                    float2 old = __half22float2(*p);
                    *p = __floats2half2_rn(old.x + frag[mt][nt][eh * 2 + 0],
                                           old.y + frag[mt][nt][eh * 2 + 1]);
                }
        __syncthreads();
    }

    // ---- softmax ----
#pragma unroll
    for (int rr = 0; rr < 6; rr++) {
        int row = wid * 6 + rr;
        int bsel = row / Hh;
        float x[32];
        float mx = -3.4e38f;
#pragma unroll
        for (int i = 0; i < 32; i++) {
            int k = lane + i * 32;
            float m = Mf[bsel * 1024 + k];
            float val = __half2float(S16[row * 1032 + k]) + AM[k];
            x[i] = (m != 0.f) ? val : NEGV;
            mx = fmaxf(mx, x[i]);
        }
#pragma unroll
        for (int o = 16; o > 0; o >>= 1) mx = fmaxf(mx, __shfl_xor_sync(~0u, mx, o));
        float sum = 0.f;
#pragma unroll
        for (int i = 0; i < 32; i++) { x[i] = __expf(x[i] - mx); sum += x[i]; }
#pragma unroll
        for (int o = 16; o > 0; o >>= 1) sum += __shfl_xor_sync(~0u, sum, o);
        float inv = 1.f / sum;
#pragma unroll
        for (int i = 0; i < 32; i++)
            S16[row * 1032 + lane + i * 32] = __float2half(x[i] * inv);
    }
    __syncthreads();

    pb_issue(sbase, PB0, j, 0, tid);

    // ---- write A fp16 ----
#pragma unroll
    for (int it = 0; it < 24; it++) {
        int idx = tid + it * 256;
        int row = idx >> 7, g = idx & 127;
        *(uint4*)(g_A16 + (((size_t)row) << 20) + ((size_t)j << 10) + g * 8) =
            *(uint4*)&S16[row * 1032 + g * 8];
    }

    // ---- phase C: attn = A·pb, A fragments ldmatrix'd straight from S16 ----
    float facc[3][4];
#pragma unroll
    for (int mt = 0; mt < 3; mt++)
#pragma unroll
        for (int e = 0; e < 4; e++) facc[mt][e] = 0.f;
    const int w16 = wid * 16;
    for (int c = 0; c < 8; c++) {
        const uint32_t cur = (c & 1) ? PB1 : PB0;
        const int k0 = c * 128;
        if (c + 1 < 8) {
            pb_issue(sbase, (c & 1) ? PB0 : PB1, j, (c + 1) * 128, tid);
            cpa_wait1();
        } else {
            cpa_wait0();
        }
        __syncthreads();
#pragma unroll
        for (int ks = 0; ks < 8; ks++) {
            uint32_t bt[2];
            uint32_t boff = SWZ((ks * 16 + (lane & 15)) * 128 + w16);
            ldmx2t(bt, sbase + cur + boff);
#pragma unroll
            for (int mt = 0; mt < 3; mt++) {
                uint32_t a4[4];
                uint32_t aoff = (uint32_t)((mt * 16 + (lane & 15)) * 2064 +
                                           (k0 + ks * 16 + (lane >> 4) * 8) * 2);
                ldmx4(a4, sbase + aoff);
                mmah(facc[mt], a4, bt);
            }
        }
    }
    {
        int d = wid * 8 + (lane & 3) * 2;
#pragma unroll
        for (int mt = 0; mt < 3; mt++)
#pragma unroll
            for (int half = 0; half < 2; half++) {
                int bh = mt * 16 + (lane >> 2) + half * 8;
                int b = bh / Hh, h = bh % Hh;
                size_t o = ((size_t)(b * 1024 + j)) * 768 + h * 64 + d;
                g_attn[o]     = facc[mt][half * 2 + 0];
                g_attn[o + 1] = facc[mt][half * 2 + 1];
            }
    }
}

// ---------------------------------------------------------------------------
// av: x16[0] = fp16(attn_pb + A·vw). Grid (4, 48), jtile = blockIdx.x + x0.
// ---------------------------------------------------------------------------
__device__ __forceinline__ void av_issue(uint32_t sbase, uint32_t bufoff,
                                         int bh, int j0, int k0, int tid) {
#pragma unroll
    for (int it = 0; it < 12; it++) {
        int idx = tid + it * 256;
        if (idx < 2048) {
            int row = idx >> 4, q = idx & 15;
            cpa16(sbase + bufoff + SWZ256(row * 256 + q * 16),
                  g_A16 + (((size_t)bh) << 20) +
                  ((size_t)(j0 + row) << 10) + k0 + q * 8);
        } else {
            int rc = idx - 2048;
            int d = rc >> 4, q = rc & 15;
            cpa16(sbase + bufoff + 32768u + SWZ256(d * 256 + q * 16),
                  g_vwt16 + ((size_t)bh * 64 + d) * 1024 + k0 + q * 8);
        }
    }
    cpa_commit();
}

__global__ __launch_bounds__(256) void av_mma_kernel(int x0) {
    extern __shared__ __align__(128) char smem[];
    const uint32_t sbase = smem_to_u32(smem);
    const int tid = threadIdx.x, wid = tid >> 5, lane = tid & 31;
    const int bh = blockIdx.y, j0 = (blockIdx.x + x0) * 128;

    float facc[8][4];
#pragma unroll
    for (int a = 0; a < 8; a++)
#pragma unroll
        for (int b = 0; b < 4; b++) facc[a][b] = 0.f;

    av_issue(sbase, 0, bh, j0, 0, tid);
    for (int c = 0; c < 8; c++) {
        const uint32_t cur = (c & 1) * 49152u;
        if (c + 1 < 8) {
            av_issue(sbase, ((c & 1) ^ 1) * 49152u, bh, j0, (c + 1) * 128, tid);
            cpa_wait1();
        } else {
            cpa_wait0();
        }
        __syncthreads();
        const uint32_t Ac = cur, Vc = cur + 32768u;
#pragma unroll
        for (int ks = 0; ks < 8; ks++) {
            uint32_t a4[4];
            uint32_t aoff = SWZ256((wid * 16 + (lane & 15)) * 256 +
                                   (ks * 2 + (lane >> 4)) * 16);
            ldmx4(a4, sbase + Ac + aoff);
#pragma unroll
            for (int np = 0; np < 4; np++) {
                uint32_t boff = SWZ256((np * 16 + (lane >> 4) * 8 + (lane & 7)) * 256 +
                                       (ks * 2 + ((lane >> 3) & 1)) * 16);
                uint32_t b4[4];
                ldmx4(b4, sbase + Vc + boff);
                mmah(facc[np * 2 + 0], a4, b4);
                mmah(facc[np * 2 + 1], a4, b4 + 2);
            }
        }
        __syncthreads();
    }
    const int b = bh / Hh, h = bh % Hh;
#pragma unroll
    for (int nt = 0; nt < 8; nt++) {
        int d = nt * 8 + (lane & 3) * 2;
#pragma unroll
        for (int half = 0; half < 2; half++) {
            int s = j0 + wid * 16 + (lane >> 2) + half * 8;
            size_t o = ((size_t)(b * 1024 + s)) * 768 + h * 64 + d;
            float v0 = g_attn[o]     + facc[nt][half * 2 + 0];
            float v1 = g_attn[o + 1] + facc[nt][half * 2 + 1];
            *(uint32_t*)(g_x16 + o) = hpack(v0, v1);
        }
    }
}

// ---------------------------------------------------------------------------
extern "C" void kernel_launch(void* const* d_in, const int* in_sizes, int n_in,
                              void* d_out, int out_size) {
    const float* q     = (const float*)d_in[0];
    const float* k     = (const float*)d_in[1];
    const float* v     = (const float*)d_in[2];
    const float* amask = (const float*)d_in[3];
    const float* pb    = (const float*)d_in[4];
    const int*   vmask = (const int*)  d_in[5];
    const float* Wq    = (const float*)d_in[6];
    const float* bq    = (const float*)d_in[7];
    const float* Wk    = (const float*)d_in[8];
    const float* bk    = (const float*)d_in[9];
    const float* Wv    = (const float*)d_in[10];
    const float* bv    = (const float*)d_in[11];
    const float* Wo    = (const float*)d_in[12];
    const float* bo    = (const float*)d_in[13];
    float* out = (float*)d_out;

    const int SM_GEMM = 65536, SM_QK = 32768, SM_FUSED = 158464, SM_AV = 98304;
    static cudaStream_t s1;
    static cudaEvent_t ev_fork, ev_join, ev_gemm, ev_qk2, ev_f1, ev_av1;
    static bool attr_done = false;
    if (!attr_done) {
        cudaFuncSetAttribute(gemm_mma_kernel, cudaFuncAttributeMaxDynamicSharedMemorySize, SM_GEMM);
        cudaFuncSetAttribute(qk_mma_kernel, cudaFuncAttributeMaxDynamicSharedMemorySize, SM_QK);
        cudaFuncSetAttribute(fused48_kernel, cudaFuncAttributeMaxDynamicSharedMemorySize, SM_FUSED);
        cudaFuncSetAttribute(av_mma_kernel, cudaFuncAttributeMaxDynamicSharedMemorySize, SM_AV);
        cudaStreamCreateWithFlags(&s1, cudaStreamNonBlocking);
        cudaEventCreateWithFlags(&ev_fork, cudaEventDisableTiming);
        cudaEventCreateWithFlags(&ev_join, cudaEventDisableTiming);
        cudaEventCreateWithFlags(&ev_gemm, cudaEventDisableTiming);
        cudaEventCreateWithFlags(&ev_qk2, cudaEventDisableTiming);
        cudaEventCreateWithFlags(&ev_f1, cudaEventDisableTiming);
        cudaEventCreateWithFlags(&ev_av1, cudaEventDisableTiming);
        attr_done = true;
    }

    const int n4 = 4096 * 768 / 4;
    const int pb4 = 1024 * 1024 * 64 / 4;

    cudaEventRecord(ev_fork, (cudaStream_t)0);
    cudaStreamWaitEvent(s1, ev_fork, 0);
    pbconv_kernel<<<512, 256, 0, s1>>>(pb, pb4);
    cudaEventRecord(ev_join, s1);

    conv16_kernel<<<dim3(n4 / 256, 3), 256>>>(q, k, v, n4);
    dim3 tthr(32, 32), tgrd(24, 24, 4);
    transpose_conv_kernel<<<tgrd, tthr>>>(Wq, Wk, Wv, Wo);
    gemm_mma_kernel<<<dim3(6, 32, 3), 256, SM_GEMM>>>(bq, bk, bv, nullptr, 0);
    cudaEventRecord(ev_gemm, (cudaStream_t)0);

    cudaStreamWaitEvent(s1, ev_gemm, 0);
    qk_mma_kernel<<<dim3(8, 4, 48), 256, SM_QK, s1>>>(4);
    cudaEventRecord(ev_qk2, s1);

    qk_mma_kernel<<<dim3(8, 4, 48), 256, SM_QK>>>(0);
    cudaStreamWaitEvent((cudaStream_t)0, ev_join, 0);
    fused48_kernel<<<512, 256, SM_FUSED>>>(amask, vmask, 0);
    cudaEventRecord(ev_f1, (cudaStream_t)0);
    cudaStreamWaitEvent((cudaStream_t)0, ev_qk2, 0);
    fused48_kernel<<<512, 256, SM_FUSED>>>(amask, vmask, 512);

    cudaStreamWaitEvent(s1, ev_f1, 0);
    av_mma_kernel<<<dim3(4, 48), 256, SM_AV, s1>>>(0);
    cudaEventRecord(ev_av1, s1);

    av_mma_kernel<<<dim3(4, 48), 256, SM_AV>>>(4);
    cudaStreamWaitEvent((cudaStream_t)0, ev_av1, 0);
    gemm_mma_kernel<<<dim3(6, 32, 1), 256, SM_GEMM>>>(bo, nullptr, nullptr, out, 1);
}